// round 8
// baseline (speedup 1.0000x reference)
#include <cuda_runtime.h>
#include <math.h>
#include <stdint.h>

#define THREADS 128
#define BB 32
#define CC 32
#define HH 128
#define WW2 128
#define HWSZ (HH*WW2)
#define CHWSZ (CC*HWSZ)
#define NTOT (BB*CHWSZ)
#define NB_MAX 2048
#define RTOLF 1e-3f
#define ATOLF 1e-3f

// dynamic smem: weights (36864B) + input tile (41472B) + reduction (128B)
#define SW_BYTES   (CC*9*CC*4)
#define SIN_BYTES  (CC*18*18*4)
#define DSM_BYTES  (SW_BYTES + SIN_BYTES + 128)

// dopri5 tableau (f32)
#define FB21 ((float)(1.0/5.0))
#define FB31 ((float)(3.0/40.0))
#define FB32 ((float)(9.0/40.0))
#define FB41 ((float)(44.0/45.0))
#define FB42 ((float)(-56.0/15.0))
#define FB43 ((float)(32.0/9.0))
#define FB51 ((float)(19372.0/6561.0))
#define FB52 ((float)(-25360.0/2187.0))
#define FB53 ((float)(64448.0/6561.0))
#define FB54 ((float)(-212.0/729.0))
#define FB61 ((float)(9017.0/3168.0))
#define FB62 ((float)(-355.0/33.0))
#define FB63 ((float)(46732.0/5247.0))
#define FB64 ((float)(49.0/176.0))
#define FB65 ((float)(-5103.0/18656.0))
#define FCS1 ((float)(35.0/384.0))
#define FCS3 ((float)(500.0/1113.0))
#define FCS4 ((float)(125.0/192.0))
#define FCS5 ((float)(-2187.0/6784.0))
#define FCS6 ((float)(11.0/84.0))
#define FCE1 ((float)(35.0/384.0 - 1951.0/21600.0))
#define FCE3 ((float)(500.0/1113.0 - 22642.0/50085.0))
#define FCE4 ((float)(125.0/192.0 - 451.0/720.0))
#define FCE5 ((float)(-2187.0/6784.0 + 12231.0/42400.0))
#define FCE6 ((float)(11.0/84.0 - 649.0/6300.0))
#define FCE7 ((float)(-1.0/60.0))
#define FCM1 ((float)(6025192743.0/30085553152.0/2.0))
#define FCM3 ((float)(51252292925.0/65400821598.0/2.0))
#define FCM4 ((float)(-2691868925.0/45128329728.0/2.0))
#define FCM5 ((float)(187940372067.0/1594534317056.0/2.0))
#define FCM6 ((float)(-1776094331.0/19743644256.0/2.0))
#define FCM7 ((float)(11237099.0/235043384.0/2.0))

// scratch slots: 0=Y0 1=Y1 2=K1 3=K2 4=K3 5=K4 6=K5 7=K6 8=K7
__device__ float  g_mem[(size_t)9 * NTOT];
__device__ double g_pA[NB_MAX];
__device__ double g_pB[NB_MAX];
__device__ float  g_feats[BB*CC];
__device__ unsigned          g_cnt = 0;
__device__ volatile unsigned g_gen = 0;

__device__ __forceinline__ float* SLOT(int s){ return g_mem + (size_t)s * NTOT; }

__device__ __forceinline__ void gbar(int nb){
  __syncthreads();
  if (threadIdx.x == 0){
    unsigned gen = g_gen;
    __threadfence();
    if (atomicAdd(&g_cnt, 1u) == (unsigned)(nb - 1)){
      g_cnt = 0u; __threadfence(); g_gen = gen + 1u;
    } else {
      while (g_gen == gen) { __nanosleep(64); }
      __threadfence();
    }
  }
  __syncthreads();
}

__device__ __forceinline__ void red_write(double v, double* s_red, double* part){
  const int lane = threadIdx.x & 31, w = threadIdx.x >> 5;
  #pragma unroll
  for (int o = 16; o; o >>= 1) v += __shfl_down_sync(0xffffffffu, v, o);
  if (lane == 0) s_red[w] = v;
  __syncthreads();
  if (threadIdx.x == 0){
    double s = 0.0;
    #pragma unroll
    for (int i = 0; i < THREADS/32; i++) s += s_red[i];
    part[blockIdx.x] = s;
  }
  __syncthreads();
}

__device__ __forceinline__ double sum_parts(const double* part, int nb, double* s_bc){
  __syncthreads();
  if (threadIdx.x == 0){
    double s = 0.0;
    for (int i = 0; i < nb; i++) s += part[i];
    *s_bc = s;
  }
  __syncthreads();
  double r = *s_bc;
  __syncthreads();
  return r;
}

// dst = tanh(conv3x3_same(src))
// Each thread: 2 output rows x 4 cols x 8 output channels (64 outputs).
// Input rows shared across the 2 output rows; weights broadcast from smem.
__device__ void conv_tanh(const float* __restrict__ src, float* __restrict__ dst,
                          int nb, const float* __restrict__ s_w,
                          float (*s_in)[18][18])
{
  const int tid = threadIdx.x;
  const int g   = tid & 3;          // 8-channel group
  const int pg  = tid >> 2;         // 0..31
  const int hp  = pg >> 2;          // 0..7  -> output rows 2hp, 2hp+1
  const int w4  = (pg & 3) << 2;    // 0,4,8,12
  const int r0  = hp << 1;
  const ulonglong2* sw2 = (const ulonglong2*)s_w;
  const int ntiles = BB * 8 * 8;
  for (int tile = blockIdx.x; tile < ntiles; tile += nb){
    const int b = tile >> 6, th = (tile >> 3) & 7, tw = tile & 7;
    const int h0 = th*16, w0 = tw*16;
    const float* sb = src + (size_t)b * CHWSZ;
    for (int i = tid; i < CC*324; i += THREADS){
      const int ci = i / 324, rem = i - ci*324;
      const int r = rem / 18, c = rem - r*18;
      const int hy = h0 + r - 1, wx = w0 + c - 1;
      float v = 0.f;
      if (hy >= 0 && hy < HH && wx >= 0 && wx < WW2) v = sb[ci*HWSZ + hy*WW2 + wx];
      s_in[ci][r][c] = v;
    }
    __syncthreads();

    unsigned long long acc[2][4][4];
    #pragma unroll
    for (int rr = 0; rr < 2; rr++)
      #pragma unroll
      for (int px = 0; px < 4; px++)
        #pragma unroll
        for (int j = 0; j < 4; j++) acc[rr][px][j] = 0ULL;

    #pragma unroll 1
    for (int ci = 0; ci < CC; ci++){
      const int wbase = ci*72 + g*2;   // ulonglong2 units
      // 4 input rows x 6 cols, duplicated into f32x2 lanes
      unsigned long long vd[4][6];
      #pragma unroll
      for (int ir = 0; ir < 4; ir++)
        #pragma unroll
        for (int c2 = 0; c2 < 6; c2++){
          const unsigned u = __float_as_uint(s_in[ci][r0+ir][w4+c2]);
          asm("mov.b64 %0, {%1, %1};" : "=l"(vd[ir][c2]) : "r"(u));
        }
      #pragma unroll
      for (int dr = 0; dr < 3; dr++){
        #pragma unroll
        for (int dc = 0; dc < 3; dc++){
          const int k = dr*3 + dc;
          const ulonglong2 wA = sw2[wbase + k*8];
          const ulonglong2 wB = sw2[wbase + k*8 + 1];
          #pragma unroll
          for (int px = 0; px < 4; px++){
            asm("fma.rn.f32x2 %0, %1, %2, %0;" : "+l"(acc[0][px][0]) : "l"(vd[dr  ][px+dc]), "l"(wA.x));
            asm("fma.rn.f32x2 %0, %1, %2, %0;" : "+l"(acc[0][px][1]) : "l"(vd[dr  ][px+dc]), "l"(wA.y));
            asm("fma.rn.f32x2 %0, %1, %2, %0;" : "+l"(acc[0][px][2]) : "l"(vd[dr  ][px+dc]), "l"(wB.x));
            asm("fma.rn.f32x2 %0, %1, %2, %0;" : "+l"(acc[0][px][3]) : "l"(vd[dr  ][px+dc]), "l"(wB.y));
            asm("fma.rn.f32x2 %0, %1, %2, %0;" : "+l"(acc[1][px][0]) : "l"(vd[dr+1][px+dc]), "l"(wA.x));
            asm("fma.rn.f32x2 %0, %1, %2, %0;" : "+l"(acc[1][px][1]) : "l"(vd[dr+1][px+dc]), "l"(wA.y));
            asm("fma.rn.f32x2 %0, %1, %2, %0;" : "+l"(acc[1][px][2]) : "l"(vd[dr+1][px+dc]), "l"(wB.x));
            asm("fma.rn.f32x2 %0, %1, %2, %0;" : "+l"(acc[1][px][3]) : "l"(vd[dr+1][px+dc]), "l"(wB.y));
          }
        }
      }
    }

    // epilogue: coalesced float4 stores (4 px per channel per row)
    #pragma unroll
    for (int rr = 0; rr < 2; rr++){
      float* db = dst + (size_t)b * CHWSZ + (h0+r0+rr)*WW2 + (w0+w4);
      #pragma unroll
      for (int j = 0; j < 4; j++){
        float4 vlo, vhi;
        float* plo = &vlo.x; float* phi = &vhi.x;
        #pragma unroll
        for (int px = 0; px < 4; px++){
          unsigned lo, hi;
          asm("mov.b64 {%0, %1}, %2;" : "=r"(lo), "=r"(hi) : "l"(acc[rr][px][j]));
          plo[px] = tanhf(__uint_as_float(lo));
          phi[px] = tanhf(__uint_as_float(hi));
        }
        const int co = g*8 + j*2;
        *(float4*)(db + (size_t)co     * HWSZ) = vlo;
        *(float4*)(db + (size_t)(co+1) * HWSZ) = vhi;
      }
    }
    __syncthreads();
  }
  gbar(nb);
}

template<int NK>
__device__ void combine(float* __restrict__ dst, const float* __restrict__ base,
                        float dt, const float* const* ks, const float* cf, int nb)
{
  const int gid = blockIdx.x*THREADS + threadIdx.x, nthr = nb*THREADS;
  const float4* b4 = (const float4*)base;
  float4* d4 = (float4*)dst;
  for (int i = gid; i < NTOT/4; i += nthr){
    float4 y = b4[i];
    float sx=0.f, sy=0.f, sz=0.f, sw=0.f;
    #pragma unroll
    for (int j = 0; j < NK; j++){
      float4 k = ((const float4*)ks[j])[i];
      const float c = cf[j];
      sx = fmaf(c,k.x,sx); sy = fmaf(c,k.y,sy); sz = fmaf(c,k.z,sz); sw = fmaf(c,k.w,sw);
    }
    float4 o;
    o.x = fmaf(dt,sx,y.x); o.y = fmaf(dt,sy,y.y); o.z = fmaf(dt,sz,y.z); o.w = fmaf(dt,sw,y.w);
    d4[i] = o;
  }
  gbar(nb);
}

__global__ void __launch_bounds__(THREADS, 2)
odenet_kernel(const float* __restrict__ x, const float* __restrict__ Wconv,
              const float* __restrict__ Wout, const float* __restrict__ bout,
              float* __restrict__ out, int nb)
{
  extern __shared__ char dsm[];
  float* s_w = (float*)dsm;
  float (*s_in)[18][18] = (float(*)[18][18])(dsm + SW_BYTES);
  double* s_red = (double*)(dsm + SW_BYTES + SIN_BYTES);
  double* s_bc  = s_red + 8;

  const int gid = blockIdx.x*THREADS + threadIdx.x, nthr = nb*THREADS;
  const int tid = threadIdx.x;

  // load + transpose weights into shared: s_w[ci*288 + k*32 + co]
  for (int i = tid; i < CC*CC*9; i += THREADS){
    const int ci = i / 288, rem = i - ci*288;
    const int k = rem >> 5, co = rem & 31;
    s_w[i] = Wconv[(co*CC + ci)*9 + k];
  }
  // pad x: Y0 = concat(x, zeros)
  {
    float* Y = SLOT(0);
    for (int i = gid; i < NTOT; i += nthr){
      const int c = (i >> 14) & 31, b = i >> 19;
      float v = 0.f;
      if (c < 3) v = x[(size_t)(b*3 + c)*HWSZ + (i & (HWSZ-1))];
      Y[i] = v;
    }
  }
  gbar(nb);

  int iY0=0, iY1=1, iK1=2, iK7=8;

  conv_tanh(SLOT(iY0), SLOT(iK1), nb, s_w, s_in);     // f0

  // initial step size (Hairer, order 4)
  {
    const float* Y = SLOT(iY0); const float* F = SLOT(iK1);
    double a=0.0, b=0.0;
    for (int i = gid; i < NTOT; i += nthr){
      const float yi = Y[i], fi = F[i];
      const float sc = ATOLF + RTOLF*fabsf(yi);
      const float r0 = yi/sc, r1 = fi/sc;
      a += (double)r0*r0; b += (double)r1*r1;
    }
    red_write(a, s_red, g_pA); red_write(b, s_red, g_pB);
    gbar(nb);
  }
  const float d0 = sqrtf((float)sum_parts(g_pA, nb, s_bc));
  const float d1 = sqrtf((float)sum_parts(g_pB, nb, s_bc));
  const float h0 = (d0 < 1e-5f || d1 < 1e-5f) ? 1e-6f : 0.01f*d0/d1;
  { const float* ks[1] = { SLOT(iK1) }; const float cf[1] = { 1.f };
    combine<1>(SLOT(iY1), SLOT(iY0), h0, ks, cf, nb); }
  conv_tanh(SLOT(iY1), SLOT(3), nb, s_w, s_in);       // f1 into K2
  {
    const float* Y = SLOT(iY0); const float* F0 = SLOT(iK1); const float* F1 = SLOT(3);
    double a = 0.0;
    for (int i = gid; i < NTOT; i += nthr){
      const float sc = ATOLF + RTOLF*fabsf(Y[i]);
      const float r = (F1[i] - F0[i]) / sc;
      a += (double)r*r;
    }
    red_write(a, s_red, g_pA); gbar(nb);
  }
  const float d2 = sqrtf((float)sum_parts(g_pA, nb, s_bc)) / h0;
  float h1;
  if (d1 <= 1e-15f && d2 <= 1e-15f) h1 = fmaxf(1e-6f, h0*1e-3f);
  else                              h1 = powf(0.01f / fmaxf(d1, d2), 0.2f);
  float dt = fminf(100.f*h0, h1);

  float t = 0.f, last_t = 0.f, dt_used = dt;
  int any = 0, iter = 0;

  while (t < 1.0f && iter < 1000 && dt > 0.f){
    iter++;
    { const float* ks[1] = { SLOT(iK1) }; const float cf[1] = { FB21 };
      combine<1>(SLOT(iY1), SLOT(iY0), dt, ks, cf, nb); }
    conv_tanh(SLOT(iY1), SLOT(3), nb, s_w, s_in);
    { const float* ks[2] = { SLOT(iK1), SLOT(3) }; const float cf[2] = { FB31, FB32 };
      combine<2>(SLOT(iY1), SLOT(iY0), dt, ks, cf, nb); }
    conv_tanh(SLOT(iY1), SLOT(4), nb, s_w, s_in);
    { const float* ks[3] = { SLOT(iK1), SLOT(3), SLOT(4) };
      const float cf[3] = { FB41, FB42, FB43 };
      combine<3>(SLOT(iY1), SLOT(iY0), dt, ks, cf, nb); }
    conv_tanh(SLOT(iY1), SLOT(5), nb, s_w, s_in);
    { const float* ks[4] = { SLOT(iK1), SLOT(3), SLOT(4), SLOT(5) };
      const float cf[4] = { FB51, FB52, FB53, FB54 };
      combine<4>(SLOT(iY1), SLOT(iY0), dt, ks, cf, nb); }
    conv_tanh(SLOT(iY1), SLOT(6), nb, s_w, s_in);
    { const float* ks[5] = { SLOT(iK1), SLOT(3), SLOT(4), SLOT(5), SLOT(6) };
      const float cf[5] = { FB61, FB62, FB63, FB64, FB65 };
      combine<5>(SLOT(iY1), SLOT(iY0), dt, ks, cf, nb); }
    conv_tanh(SLOT(iY1), SLOT(7), nb, s_w, s_in);
    { const float* ks[5] = { SLOT(iK1), SLOT(4), SLOT(5), SLOT(6), SLOT(7) };
      const float cf[5] = { FCS1, FCS3, FCS4, FCS5, FCS6 };
      combine<5>(SLOT(iY1), SLOT(iY0), dt, ks, cf, nb); }   // y1
    conv_tanh(SLOT(iY1), SLOT(iK7), nb, s_w, s_in);         // k7 = f(y1)

    // error ratio^2 sum
    {
      const float* Y0 = SLOT(iY0); const float* Y1 = SLOT(iY1);
      const float* K1 = SLOT(iK1); const float* K3 = SLOT(4);
      const float* K4 = SLOT(5);   const float* K5 = SLOT(6);
      const float* K6 = SLOT(7);   const float* K7 = SLOT(iK7);
      double a = 0.0;
      for (int i = gid; i < NTOT; i += nthr){
        float e = FCE1*K1[i];
        e = fmaf(FCE3, K3[i], e); e = fmaf(FCE4, K4[i], e);
        e = fmaf(FCE5, K5[i], e); e = fmaf(FCE6, K6[i], e);
        e = fmaf(FCE7, K7[i], e); e *= dt;
        const float tol = ATOLF + RTOLF*fmaxf(fabsf(Y0[i]), fabsf(Y1[i]));
        const float r = e / tol;
        a += (double)r*r;
      }
      red_write(a, s_red, g_pA); gbar(nb);
    }
    const double sum = sum_parts(g_pA, nb, s_bc);
    const float ratio = sqrtf((float)(sum / (double)NTOT));
    const float dfac = (ratio < 1.f) ? 1.0f : 0.2f;
    const float factor = fminf(10.f, fmaxf(0.9f * powf(ratio, -0.2f), dfac));
    const float new_dt = dt * factor;
    if (ratio <= 1.f){
      any = 1; dt_used = dt; last_t = t; t = t + dt;
      if (t >= 1.0f){ dt = new_dt; break; }    // final step: keep buffers unswapped
      int tmp = iY0; iY0 = iY1; iY1 = tmp;
      tmp = iK1; iK1 = iK7; iK7 = tmp;
    }
    dt = new_dt;
  }

  // interpolate to t=1, fused with global spatial max
  {
    const float xr = any ? (1.0f - last_t) / (t - last_t) : 0.f;
    const float dtu = dt_used;
    const float* Y0 = SLOT(iY0); const float* Y1 = SLOT(iY1);
    const float* K1 = SLOT(iK1); const float* K3 = SLOT(4);
    const float* K4 = SLOT(5);   const float* K5 = SLOT(6);
    const float* K6 = SLOT(7);   const float* K7 = SLOT(iK7);
    const int gw = gid >> 5, lane = threadIdx.x & 31, nw = nthr >> 5;
    for (int p = gw; p < BB*CC; p += nw){
      const size_t base = (size_t)p * HWSZ;
      float m = -3.402823466e38f;
      for (int i = lane; i < HWSZ; i += 32){
        const size_t idx = base + i;
        const float y0 = Y0[idx];
        float v = y0;
        if (any){
          const float y1 = Y1[idx];
          const float k1 = K1[idx], k7 = K7[idx];
          float s = FCM1*k1;
          s = fmaf(FCM3, K3[idx], s); s = fmaf(FCM4, K4[idx], s);
          s = fmaf(FCM5, K5[idx], s); s = fmaf(FCM6, K6[idx], s);
          s = fmaf(FCM7, k7, s);
          const float ym = fmaf(dtu, s, y0);
          const float dy0 = k1*dtu, dy1 = k7*dtu;
          const float ca = 2.f*(dy1 - dy0) - 8.f*(y1 + y0) + 16.f*ym;
          const float cb = 5.f*dy0 - 3.f*dy1 + 18.f*y0 + 14.f*y1 - 32.f*ym;
          const float cc = -4.f*dy0 + dy1 - 11.f*y0 - 5.f*y1 + 16.f*ym;
          v = fmaf(fmaf(fmaf(fmaf(ca, xr, cb), xr, cc), xr, dy0), xr, y0);
        }
        m = fmaxf(m, v);
      }
      #pragma unroll
      for (int o = 16; o; o >>= 1) m = fmaxf(m, __shfl_down_sync(0xffffffffu, m, o));
      if (lane == 0) g_feats[p] = m;
    }
    gbar(nb);
  }

  // linear head: out[b][n] = feats[b] . Wout[n] + bout[n]
  for (int idx = gid; idx < BB*1000; idx += nthr){
    const int b = idx / 1000, n = idx - b*1000;
    const float* f = g_feats + b*CC;
    const float* w = Wout + n*CC;
    float s = bout[n];
    #pragma unroll
    for (int c = 0; c < CC; c++) s = fmaf(f[c], __ldg(w + c), s);
    out[idx] = s;
  }
}

extern "C" void kernel_launch(void* const* d_in, const int* in_sizes, int n_in,
                              void* d_out, int out_size)
{
  const float* x     = (const float*)d_in[0];
  const float* Wconv = (const float*)d_in[1];
  const float* Wout  = (const float*)d_in[2];
  const float* bout  = (const float*)d_in[3];
  float* out = (float*)d_out;

  cudaFuncSetAttribute(odenet_kernel, cudaFuncAttributeMaxDynamicSharedMemorySize, DSM_BYTES);

  int dev = 0; cudaGetDevice(&dev);
  int smCount = 0;
  cudaDeviceGetAttribute(&smCount, cudaDevAttrMultiProcessorCount, dev);
  int bpm = 0;
  cudaOccupancyMaxActiveBlocksPerMultiprocessor(&bpm, odenet_kernel, THREADS, DSM_BYTES);
  if (bpm < 1) bpm = 1;
  int nb = smCount * bpm;
  if (nb > NB_MAX) nb = NB_MAX;
  if (nb < 1) nb = 1;

  odenet_kernel<<<nb, THREADS, DSM_BYTES>>>(x, Wconv, Wout, bout, out, nb);
}

// round 9
// speedup vs baseline: 1.1921x; 1.1921x over previous
#include <cuda_runtime.h>
#include <math.h>
#include <stdint.h>

#define THREADS 256
#define BB 32
#define CC 32
#define HH 128
#define WW2 128
#define HWSZ (HH*WW2)
#define CHWSZ (CC*HWSZ)
#define NTOT (BB*CHWSZ)
#define NB_MAX 2048
#define RTOLF 1e-3f
#define ATOLF 1e-3f

// dynamic smem: weights (36864B) + padded input tile 32x18x20 (46080B) + reduction
#define SW_BYTES   (CC*9*CC*4)
#define SIN_BYTES  (CC*18*20*4)
#define DSM_BYTES  (SW_BYTES + SIN_BYTES + 128)

// dopri5 tableau (f32)
#define FB21 ((float)(1.0/5.0))
#define FB31 ((float)(3.0/40.0))
#define FB32 ((float)(9.0/40.0))
#define FB41 ((float)(44.0/45.0))
#define FB42 ((float)(-56.0/15.0))
#define FB43 ((float)(32.0/9.0))
#define FB51 ((float)(19372.0/6561.0))
#define FB52 ((float)(-25360.0/2187.0))
#define FB53 ((float)(64448.0/6561.0))
#define FB54 ((float)(-212.0/729.0))
#define FB61 ((float)(9017.0/3168.0))
#define FB62 ((float)(-355.0/33.0))
#define FB63 ((float)(46732.0/5247.0))
#define FB64 ((float)(49.0/176.0))
#define FB65 ((float)(-5103.0/18656.0))
#define FCS1 ((float)(35.0/384.0))
#define FCS3 ((float)(500.0/1113.0))
#define FCS4 ((float)(125.0/192.0))
#define FCS5 ((float)(-2187.0/6784.0))
#define FCS6 ((float)(11.0/84.0))
#define FCE1 ((float)(35.0/384.0 - 1951.0/21600.0))
#define FCE3 ((float)(500.0/1113.0 - 22642.0/50085.0))
#define FCE4 ((float)(125.0/192.0 - 451.0/720.0))
#define FCE5 ((float)(-2187.0/6784.0 + 12231.0/42400.0))
#define FCE6 ((float)(11.0/84.0 - 649.0/6300.0))
#define FCE7 ((float)(-1.0/60.0))
#define FCM1 ((float)(6025192743.0/30085553152.0/2.0))
#define FCM3 ((float)(51252292925.0/65400821598.0/2.0))
#define FCM4 ((float)(-2691868925.0/45128329728.0/2.0))
#define FCM5 ((float)(187940372067.0/1594534317056.0/2.0))
#define FCM6 ((float)(-1776094331.0/19743644256.0/2.0))
#define FCM7 ((float)(11237099.0/235043384.0/2.0))

// scratch slots: 0=Y0 1=Y1 2=K1 3=K2 4=K3 5=K4 6=K5 7=K6 8=K7
__device__ float  g_mem[(size_t)9 * NTOT];
__device__ double g_pA[NB_MAX];
__device__ double g_pB[NB_MAX];
__device__ float  g_feats[BB*CC];
__device__ unsigned          g_cnt = 0;
__device__ volatile unsigned g_gen = 0;

__device__ __forceinline__ float* SLOT(int s){ return g_mem + (size_t)s * NTOT; }

__device__ __forceinline__ void gbar(int nb){
  __syncthreads();
  if (threadIdx.x == 0){
    unsigned gen = g_gen;
    __threadfence();
    if (atomicAdd(&g_cnt, 1u) == (unsigned)(nb - 1)){
      g_cnt = 0u; __threadfence(); g_gen = gen + 1u;
    } else {
      while (g_gen == gen) { __nanosleep(64); }
      __threadfence();
    }
  }
  __syncthreads();
}

__device__ __forceinline__ void red_write(double v, double* s_red, double* part){
  const int lane = threadIdx.x & 31, w = threadIdx.x >> 5;
  #pragma unroll
  for (int o = 16; o; o >>= 1) v += __shfl_down_sync(0xffffffffu, v, o);
  if (lane == 0) s_red[w] = v;
  __syncthreads();
  if (threadIdx.x == 0){
    double s = 0.0;
    #pragma unroll
    for (int i = 0; i < THREADS/32; i++) s += s_red[i];
    part[blockIdx.x] = s;
  }
  __syncthreads();
}

__device__ __forceinline__ double sum_parts(const double* part, int nb, double* s_bc){
  __syncthreads();
  if (threadIdx.x == 0){
    double s = 0.0;
    for (int i = 0; i < nb; i++) s += part[i];
    *s_bc = s;
  }
  __syncthreads();
  double r = *s_bc;
  __syncthreads();
  return r;
}

// dst = tanh(conv3x3_same( base + dt * sum_j cf[j]*ks[j] ))   (NK==0: plain src)
// The stage-combine is fused into the halo load; each thread computes
// 1 row x 4 cols x 8 output channels. Padded smem rows (20 floats) allow
// vectorized LDS.128/LDS.64 input loads.
template<int NK>
__device__ void conv_tanh_f(const float* __restrict__ base,
                            const float* const* ks, const float* cf, float dt,
                            float* __restrict__ dst,
                            int nb, const float* __restrict__ s_w,
                            float* __restrict__ s_inp)
{
  const int tid = threadIdx.x;
  const int g   = tid & 3;          // 8-channel group
  const int pg  = tid >> 2;         // 0..63
  const int hh  = pg >> 2;          // 0..15
  const int w4  = (pg & 3) << 2;    // 0,4,8,12
  const ulonglong2* sw2 = (const ulonglong2*)s_w;
  const int ntiles = BB * 8 * 8;
  for (int tile = blockIdx.x; tile < ntiles; tile += nb){
    const int b = tile >> 6, th = (tile >> 3) & 7, tw = tile & 7;
    const int h0 = th*16, w0 = tw*16;
    const size_t boff = (size_t)b * CHWSZ;
    // halo load with fused stage-combine
    for (int i = tid; i < CC*324; i += THREADS){
      const int ci = i / 324, rem = i - ci*324;
      const int r = rem / 18, c = rem - r*18;
      const int hy = h0 + r - 1, wx = w0 + c - 1;
      float v = 0.f;
      if (hy >= 0 && hy < HH && wx >= 0 && wx < WW2){
        const size_t bidx = boff + (size_t)ci*HWSZ + hy*WW2 + wx;
        v = base[bidx];
        if (NK > 0){
          float s = cf[0] * ks[0][bidx];
          #pragma unroll
          for (int j = 1; j < NK; j++) s = fmaf(cf[j], ks[j][bidx], s);
          v = fmaf(dt, s, v);
        }
      }
      s_inp[ci*360 + r*20 + c] = v;
    }
    __syncthreads();

    unsigned long long acc[4][4];
    #pragma unroll
    for (int px = 0; px < 4; px++)
      #pragma unroll
      for (int j = 0; j < 4; j++) acc[px][j] = 0ULL;

    #pragma unroll 1
    for (int ci = 0; ci < CC; ci++){
      const float* rowp = s_inp + ci*360 + hh*20 + w4;
      unsigned long long vd[3][6];
      #pragma unroll
      for (int dr = 0; dr < 3; dr++){
        const float4 a  = *(const float4*)(rowp + dr*20);
        const float2 b2 = *(const float2*)(rowp + dr*20 + 4);
        const unsigned u0 = __float_as_uint(a.x),  u1 = __float_as_uint(a.y);
        const unsigned u2 = __float_as_uint(a.z),  u3 = __float_as_uint(a.w);
        const unsigned u4 = __float_as_uint(b2.x), u5 = __float_as_uint(b2.y);
        asm("mov.b64 %0, {%1, %1};" : "=l"(vd[dr][0]) : "r"(u0));
        asm("mov.b64 %0, {%1, %1};" : "=l"(vd[dr][1]) : "r"(u1));
        asm("mov.b64 %0, {%1, %1};" : "=l"(vd[dr][2]) : "r"(u2));
        asm("mov.b64 %0, {%1, %1};" : "=l"(vd[dr][3]) : "r"(u3));
        asm("mov.b64 %0, {%1, %1};" : "=l"(vd[dr][4]) : "r"(u4));
        asm("mov.b64 %0, {%1, %1};" : "=l"(vd[dr][5]) : "r"(u5));
      }
      const int wbase = ci*72 + g*2;   // ulonglong2 units
      #pragma unroll
      for (int dr = 0; dr < 3; dr++){
        #pragma unroll
        for (int dc = 0; dc < 3; dc++){
          const int k = dr*3 + dc;
          const ulonglong2 wA = sw2[wbase + k*8];
          const ulonglong2 wB = sw2[wbase + k*8 + 1];
          #pragma unroll
          for (int px = 0; px < 4; px++){
            asm("fma.rn.f32x2 %0, %1, %2, %0;" : "+l"(acc[px][0]) : "l"(vd[dr][px+dc]), "l"(wA.x));
            asm("fma.rn.f32x2 %0, %1, %2, %0;" : "+l"(acc[px][1]) : "l"(vd[dr][px+dc]), "l"(wA.y));
            asm("fma.rn.f32x2 %0, %1, %2, %0;" : "+l"(acc[px][2]) : "l"(vd[dr][px+dc]), "l"(wB.x));
            asm("fma.rn.f32x2 %0, %1, %2, %0;" : "+l"(acc[px][3]) : "l"(vd[dr][px+dc]), "l"(wB.y));
          }
        }
      }
    }

    float* db = dst + boff + (h0+hh)*WW2 + (w0+w4);
    #pragma unroll
    for (int j = 0; j < 4; j++){
      float4 vlo, vhi;
      float* plo = &vlo.x; float* phi = &vhi.x;
      #pragma unroll
      for (int px = 0; px < 4; px++){
        unsigned lo, hi;
        asm("mov.b64 {%0, %1}, %2;" : "=r"(lo), "=r"(hi) : "l"(acc[px][j]));
        plo[px] = tanhf(__uint_as_float(lo));
        phi[px] = tanhf(__uint_as_float(hi));
      }
      const int co = g*8 + j*2;
      *(float4*)(db + (size_t)co     * HWSZ) = vlo;
      *(float4*)(db + (size_t)(co+1) * HWSZ) = vhi;
    }
    __syncthreads();
  }
  gbar(nb);
}

template<int NK>
__device__ void combine(float* __restrict__ dst, const float* __restrict__ base,
                        float dt, const float* const* ks, const float* cf, int nb)
{
  const int gid = blockIdx.x*THREADS + threadIdx.x, nthr = nb*THREADS;
  const float4* b4 = (const float4*)base;
  float4* d4 = (float4*)dst;
  for (int i = gid; i < NTOT/4; i += nthr){
    float4 y = b4[i];
    float sx=0.f, sy=0.f, sz=0.f, sw=0.f;
    #pragma unroll
    for (int j = 0; j < NK; j++){
      float4 k = ((const float4*)ks[j])[i];
      const float c = cf[j];
      sx = fmaf(c,k.x,sx); sy = fmaf(c,k.y,sy); sz = fmaf(c,k.z,sz); sw = fmaf(c,k.w,sw);
    }
    float4 o;
    o.x = fmaf(dt,sx,y.x); o.y = fmaf(dt,sy,y.y); o.z = fmaf(dt,sz,y.z); o.w = fmaf(dt,sw,y.w);
    d4[i] = o;
  }
  gbar(nb);
}

__global__ void __launch_bounds__(THREADS, 2)
odenet_kernel(const float* __restrict__ x, const float* __restrict__ Wconv,
              const float* __restrict__ Wout, const float* __restrict__ bout,
              float* __restrict__ out, int nb)
{
  extern __shared__ char dsm[];
  float* s_w   = (float*)dsm;
  float* s_inp = (float*)(dsm + SW_BYTES);
  double* s_red = (double*)(dsm + SW_BYTES + SIN_BYTES);
  double* s_bc  = s_red + 8;

  const int gid = blockIdx.x*THREADS + threadIdx.x, nthr = nb*THREADS;
  const int tid = threadIdx.x;

  // load + transpose weights into shared: s_w[ci*288 + k*32 + co]
  for (int i = tid; i < CC*CC*9; i += THREADS){
    const int ci = i / 288, rem = i - ci*288;
    const int k = rem >> 5, co = rem & 31;
    s_w[i] = Wconv[(co*CC + ci)*9 + k];
  }
  // pad x: Y0 = concat(x, zeros)
  {
    float* Y = SLOT(0);
    for (int i = gid; i < NTOT; i += nthr){
      const int c = (i >> 14) & 31, b = i >> 19;
      float v = 0.f;
      if (c < 3) v = x[(size_t)(b*3 + c)*HWSZ + (i & (HWSZ-1))];
      Y[i] = v;
    }
  }
  gbar(nb);

  int iY0=0, iY1=1, iK1=2, iK7=8;
  const float* nullks[1] = { (const float*)0 };
  const float  nullcf[1] = { 0.f };

  conv_tanh_f<0>(SLOT(iY0), nullks, nullcf, 0.f, SLOT(iK1), nb, s_w, s_inp);   // f0

  // initial step size (Hairer, order 4)
  {
    const float* Y = SLOT(iY0); const float* F = SLOT(iK1);
    double a=0.0, b=0.0;
    for (int i = gid; i < NTOT; i += nthr){
      const float yi = Y[i], fi = F[i];
      const float sc = ATOLF + RTOLF*fabsf(yi);
      const float r0 = yi/sc, r1 = fi/sc;
      a += (double)r0*r0; b += (double)r1*r1;
    }
    red_write(a, s_red, g_pA); red_write(b, s_red, g_pB);
    gbar(nb);
  }
  const float d0 = sqrtf((float)sum_parts(g_pA, nb, s_bc));
  const float d1 = sqrtf((float)sum_parts(g_pB, nb, s_bc));
  const float h0 = (d0 < 1e-5f || d1 < 1e-5f) ? 1e-6f : 0.01f*d0/d1;
  { const float* ks[1] = { SLOT(iK1) }; const float cf[1] = { 1.f };
    conv_tanh_f<1>(SLOT(iY0), ks, cf, h0, SLOT(3), nb, s_w, s_inp); }          // f1 into K2
  {
    const float* Y = SLOT(iY0); const float* F0 = SLOT(iK1); const float* F1 = SLOT(3);
    double a = 0.0;
    for (int i = gid; i < NTOT; i += nthr){
      const float sc = ATOLF + RTOLF*fabsf(Y[i]);
      const float r = (F1[i] - F0[i]) / sc;
      a += (double)r*r;
    }
    red_write(a, s_red, g_pA); gbar(nb);
  }
  const float d2 = sqrtf((float)sum_parts(g_pA, nb, s_bc)) / h0;
  float h1;
  if (d1 <= 1e-15f && d2 <= 1e-15f) h1 = fmaxf(1e-6f, h0*1e-3f);
  else                              h1 = powf(0.01f / fmaxf(d1, d2), 0.2f);
  float dt = fminf(100.f*h0, h1);

  float t = 0.f, last_t = 0.f, dt_used = dt;
  int any = 0, iter = 0;

  while (t < 1.0f && iter < 1000 && dt > 0.f){
    iter++;
    { const float* ks[1] = { SLOT(iK1) }; const float cf[1] = { FB21 };
      conv_tanh_f<1>(SLOT(iY0), ks, cf, dt, SLOT(3), nb, s_w, s_inp); }
    { const float* ks[2] = { SLOT(iK1), SLOT(3) }; const float cf[2] = { FB31, FB32 };
      conv_tanh_f<2>(SLOT(iY0), ks, cf, dt, SLOT(4), nb, s_w, s_inp); }
    { const float* ks[3] = { SLOT(iK1), SLOT(3), SLOT(4) };
      const float cf[3] = { FB41, FB42, FB43 };
      conv_tanh_f<3>(SLOT(iY0), ks, cf, dt, SLOT(5), nb, s_w, s_inp); }
    { const float* ks[4] = { SLOT(iK1), SLOT(3), SLOT(4), SLOT(5) };
      const float cf[4] = { FB51, FB52, FB53, FB54 };
      conv_tanh_f<4>(SLOT(iY0), ks, cf, dt, SLOT(6), nb, s_w, s_inp); }
    { const float* ks[5] = { SLOT(iK1), SLOT(3), SLOT(4), SLOT(5), SLOT(6) };
      const float cf[5] = { FB61, FB62, FB63, FB64, FB65 };
      conv_tanh_f<5>(SLOT(iY0), ks, cf, dt, SLOT(7), nb, s_w, s_inp); }
    { const float* ks[5] = { SLOT(iK1), SLOT(4), SLOT(5), SLOT(6), SLOT(7) };
      const float cf[5] = { FCS1, FCS3, FCS4, FCS5, FCS6 };
      combine<5>(SLOT(iY1), SLOT(iY0), dt, ks, cf, nb); }   // y1 (materialized)
    conv_tanh_f<0>(SLOT(iY1), nullks, nullcf, 0.f, SLOT(iK7), nb, s_w, s_inp); // k7

    // error ratio^2 sum
    {
      const float* Y0 = SLOT(iY0); const float* Y1 = SLOT(iY1);
      const float* K1 = SLOT(iK1); const float* K3 = SLOT(4);
      const float* K4 = SLOT(5);   const float* K5 = SLOT(6);
      const float* K6 = SLOT(7);   const float* K7 = SLOT(iK7);
      double a = 0.0;
      for (int i = gid; i < NTOT; i += nthr){
        float e = FCE1*K1[i];
        e = fmaf(FCE3, K3[i], e); e = fmaf(FCE4, K4[i], e);
        e = fmaf(FCE5, K5[i], e); e = fmaf(FCE6, K6[i], e);
        e = fmaf(FCE7, K7[i], e); e *= dt;
        const float tol = ATOLF + RTOLF*fmaxf(fabsf(Y0[i]), fabsf(Y1[i]));
        const float r = e / tol;
        a += (double)r*r;
      }
      red_write(a, s_red, g_pA); gbar(nb);
    }
    const double sum = sum_parts(g_pA, nb, s_bc);
    const float ratio = sqrtf((float)(sum / (double)NTOT));
    const float dfac = (ratio < 1.f) ? 1.0f : 0.2f;
    const float factor = fminf(10.f, fmaxf(0.9f * powf(ratio, -0.2f), dfac));
    const float new_dt = dt * factor;
    if (ratio <= 1.f){
      any = 1; dt_used = dt; last_t = t; t = t + dt;
      if (t >= 1.0f){ dt = new_dt; break; }    // final step: keep buffers unswapped
      int tmp = iY0; iY0 = iY1; iY1 = tmp;
      tmp = iK1; iK1 = iK7; iK7 = tmp;
    }
    dt = new_dt;
  }

  // interpolate to t=1, fused with global spatial max
  {
    const float xr = any ? (1.0f - last_t) / (t - last_t) : 0.f;
    const float dtu = dt_used;
    const float* Y0 = SLOT(iY0); const float* Y1 = SLOT(iY1);
    const float* K1 = SLOT(iK1); const float* K3 = SLOT(4);
    const float* K4 = SLOT(5);   const float* K5 = SLOT(6);
    const float* K6 = SLOT(7);   const float* K7 = SLOT(iK7);
    const int gw = gid >> 5, lane = threadIdx.x & 31, nw = nthr >> 5;
    for (int p = gw; p < BB*CC; p += nw){
      const size_t base = (size_t)p * HWSZ;
      float m = -3.402823466e38f;
      for (int i = lane; i < HWSZ; i += 32){
        const size_t idx = base + i;
        const float y0 = Y0[idx];
        float v = y0;
        if (any){
          const float y1 = Y1[idx];
          const float k1 = K1[idx], k7 = K7[idx];
          float s = FCM1*k1;
          s = fmaf(FCM3, K3[idx], s); s = fmaf(FCM4, K4[idx], s);
          s = fmaf(FCM5, K5[idx], s); s = fmaf(FCM6, K6[idx], s);
          s = fmaf(FCM7, k7, s);
          const float ym = fmaf(dtu, s, y0);
          const float dy0 = k1*dtu, dy1 = k7*dtu;
          const float ca = 2.f*(dy1 - dy0) - 8.f*(y1 + y0) + 16.f*ym;
          const float cb = 5.f*dy0 - 3.f*dy1 + 18.f*y0 + 14.f*y1 - 32.f*ym;
          const float cc = -4.f*dy0 + dy1 - 11.f*y0 - 5.f*y1 + 16.f*ym;
          v = fmaf(fmaf(fmaf(fmaf(ca, xr, cb), xr, cc), xr, dy0), xr, y0);
        }
        m = fmaxf(m, v);
      }
      #pragma unroll
      for (int o = 16; o; o >>= 1) m = fmaxf(m, __shfl_down_sync(0xffffffffu, m, o));
      if (lane == 0) g_feats[p] = m;
    }
    gbar(nb);
  }

  // linear head: out[b][n] = feats[b] . Wout[n] + bout[n]
  for (int idx = gid; idx < BB*1000; idx += nthr){
    const int b = idx / 1000, n = idx - b*1000;
    const float* f = g_feats + b*CC;
    const float* w = Wout + n*CC;
    float s = bout[n];
    #pragma unroll
    for (int c = 0; c < CC; c++) s = fmaf(f[c], __ldg(w + c), s);
    out[idx] = s;
  }
}

extern "C" void kernel_launch(void* const* d_in, const int* in_sizes, int n_in,
                              void* d_out, int out_size)
{
  const float* x     = (const float*)d_in[0];
  const float* Wconv = (const float*)d_in[1];
  const float* Wout  = (const float*)d_in[2];
  const float* bout  = (const float*)d_in[3];
  float* out = (float*)d_out;

  cudaFuncSetAttribute(odenet_kernel, cudaFuncAttributeMaxDynamicSharedMemorySize, DSM_BYTES);

  int dev = 0; cudaGetDevice(&dev);
  int smCount = 0;
  cudaDeviceGetAttribute(&smCount, cudaDevAttrMultiProcessorCount, dev);
  int bpm = 0;
  cudaOccupancyMaxActiveBlocksPerMultiprocessor(&bpm, odenet_kernel, THREADS, DSM_BYTES);
  if (bpm < 1) bpm = 1;
  int nb = smCount * bpm;
  if (nb > NB_MAX) nb = NB_MAX;
  if (nb < 1) nb = 1;

  odenet_kernel<<<nb, THREADS, DSM_BYTES>>>(x, Wconv, Wout, bout, out, nb);
}

// round 10
// speedup vs baseline: 1.3176x; 1.1053x over previous
#include <cuda_runtime.h>
#include <math.h>
#include <stdint.h>

#define THREADS 256
#define BB 32
#define CC 32
#define HH 128
#define WW2 128
#define HWSZ (HH*WW2)
#define CHWSZ (CC*HWSZ)
#define NTOT (BB*CHWSZ)
#define NB_MAX 2048
#define RTOLF 1e-3f
#define ATOLF 1e-3f

// dynamic smem: weights (36864B) + padded input tile 32x18x20 (46080B) + reduction
#define SW_BYTES   (CC*9*CC*4)
#define SIN_BYTES  (CC*18*20*4)
#define DSM_BYTES  (SW_BYTES + SIN_BYTES + 128)

// dopri5 tableau (f32)
#define FB21 ((float)(1.0/5.0))
#define FB31 ((float)(3.0/40.0))
#define FB32 ((float)(9.0/40.0))
#define FB41 ((float)(44.0/45.0))
#define FB42 ((float)(-56.0/15.0))
#define FB43 ((float)(32.0/9.0))
#define FB51 ((float)(19372.0/6561.0))
#define FB52 ((float)(-25360.0/2187.0))
#define FB53 ((float)(64448.0/6561.0))
#define FB54 ((float)(-212.0/729.0))
#define FB61 ((float)(9017.0/3168.0))
#define FB62 ((float)(-355.0/33.0))
#define FB63 ((float)(46732.0/5247.0))
#define FB64 ((float)(49.0/176.0))
#define FB65 ((float)(-5103.0/18656.0))
#define FCS1 ((float)(35.0/384.0))
#define FCS3 ((float)(500.0/1113.0))
#define FCS4 ((float)(125.0/192.0))
#define FCS5 ((float)(-2187.0/6784.0))
#define FCS6 ((float)(11.0/84.0))
#define FCE1 ((float)(35.0/384.0 - 1951.0/21600.0))
#define FCE3 ((float)(500.0/1113.0 - 22642.0/50085.0))
#define FCE4 ((float)(125.0/192.0 - 451.0/720.0))
#define FCE5 ((float)(-2187.0/6784.0 + 12231.0/42400.0))
#define FCE6 ((float)(11.0/84.0 - 649.0/6300.0))
#define FCE7 ((float)(-1.0/60.0))
#define FCM1 ((float)(6025192743.0/30085553152.0/2.0))
#define FCM3 ((float)(51252292925.0/65400821598.0/2.0))
#define FCM4 ((float)(-2691868925.0/45128329728.0/2.0))
#define FCM5 ((float)(187940372067.0/1594534317056.0/2.0))
#define FCM6 ((float)(-1776094331.0/19743644256.0/2.0))
#define FCM7 ((float)(11237099.0/235043384.0/2.0))

// scratch slots (indices are dynamic; 9 buffers total)
__device__ float  g_mem[(size_t)9 * NTOT];
__device__ double g_pA[NB_MAX];
__device__ double g_pB[NB_MAX];
__device__ float  g_feats[BB*CC];
__device__ unsigned          g_cnt = 0;
__device__ volatile unsigned g_gen = 0;

__device__ __forceinline__ float* SLOT(int s){ return g_mem + (size_t)s * NTOT; }

__device__ __forceinline__ void gbar(int nb){
  __syncthreads();
  if (threadIdx.x == 0){
    unsigned gen = g_gen;
    __threadfence();
    if (atomicAdd(&g_cnt, 1u) == (unsigned)(nb - 1)){
      g_cnt = 0u; __threadfence(); g_gen = gen + 1u;
    } else {
      while (g_gen == gen) { __nanosleep(64); }
      __threadfence();
    }
  }
  __syncthreads();
}

__device__ __forceinline__ void red_write(double v, double* s_red, double* part){
  const int lane = threadIdx.x & 31, w = threadIdx.x >> 5;
  #pragma unroll
  for (int o = 16; o; o >>= 1) v += __shfl_down_sync(0xffffffffu, v, o);
  if (lane == 0) s_red[w] = v;
  __syncthreads();
  if (threadIdx.x == 0){
    double s = 0.0;
    #pragma unroll
    for (int i = 0; i < THREADS/32; i++) s += s_red[i];
    part[blockIdx.x] = s;
  }
  __syncthreads();
}

__device__ __forceinline__ double sum_parts(const double* part, int nb, double* s_bc){
  __syncthreads();
  if (threadIdx.x == 0){
    double s = 0.0;
    for (int i = 0; i < nb; i++) s += part[i];
    *s_bc = s;
  }
  __syncthreads();
  double r = *s_bc;
  __syncthreads();
  return r;
}

// dst = tanh(conv3x3_same(src)); 1 row x 4 px x 8 co per thread.
// EPI=0: plain. EPI=1: also y1 = eA0 + dt*(FCS1*eA1+FCS3*eA2+FCS4*eA3+FCS5*eA4+FCS6*k6) -> dst2.
// EPI=2: also accumulate dopri error ratio^2 (eA = {Y0,Y1,K1,K3,K4,K5,K6}; K7 = local).
template<int EPI>
__device__ void conv_tanh(const float* __restrict__ src, float* __restrict__ dst,
                          float* __restrict__ dst2, const float* const* eA, float dtv,
                          int nb, const float* __restrict__ s_w,
                          float* __restrict__ s_inp, double* s_red)
{
  const int tid = threadIdx.x;
  const int g   = tid & 3;          // 8-channel group
  const int pg  = tid >> 2;         // 0..63
  const int hh  = pg >> 2;          // 0..15
  const int w4  = (pg & 3) << 2;    // 0,4,8,12
  const ulonglong2* sw2 = (const ulonglong2*)s_w;
  const int ntiles = BB * 64;
  double errA = 0.0;
  for (int tile = blockIdx.x; tile < ntiles; tile += nb){
    const int b = tile >> 6, th = (tile >> 3) & 7, tw = tile & 7;
    const int h0 = th*16, w0 = tw*16;
    const size_t boff = (size_t)b * CHWSZ;
    for (int i = tid; i < CC*324; i += THREADS){
      const int ci = i / 324, rem = i - ci*324;
      const int r = rem / 18, c = rem - r*18;
      const int hy = h0 + r - 1, wx = w0 + c - 1;
      float v = 0.f;
      if (hy >= 0 && hy < HH && wx >= 0 && wx < WW2)
        v = src[boff + (size_t)ci*HWSZ + hy*WW2 + wx];
      s_inp[ci*360 + r*20 + c] = v;
    }
    __syncthreads();

    unsigned long long acc[4][4];
    #pragma unroll
    for (int px = 0; px < 4; px++)
      #pragma unroll
      for (int j = 0; j < 4; j++) acc[px][j] = 0ULL;

    #pragma unroll 1
    for (int ci = 0; ci < CC; ci++){
      const float* rowp = s_inp + ci*360 + hh*20 + w4;
      unsigned long long vd[3][6];
      #pragma unroll
      for (int dr = 0; dr < 3; dr++){
        const float4 a  = *(const float4*)(rowp + dr*20);
        const float2 b2 = *(const float2*)(rowp + dr*20 + 4);
        const unsigned u0 = __float_as_uint(a.x),  u1 = __float_as_uint(a.y);
        const unsigned u2 = __float_as_uint(a.z),  u3 = __float_as_uint(a.w);
        const unsigned u4 = __float_as_uint(b2.x), u5 = __float_as_uint(b2.y);
        asm("mov.b64 %0, {%1, %1};" : "=l"(vd[dr][0]) : "r"(u0));
        asm("mov.b64 %0, {%1, %1};" : "=l"(vd[dr][1]) : "r"(u1));
        asm("mov.b64 %0, {%1, %1};" : "=l"(vd[dr][2]) : "r"(u2));
        asm("mov.b64 %0, {%1, %1};" : "=l"(vd[dr][3]) : "r"(u3));
        asm("mov.b64 %0, {%1, %1};" : "=l"(vd[dr][4]) : "r"(u4));
        asm("mov.b64 %0, {%1, %1};" : "=l"(vd[dr][5]) : "r"(u5));
      }
      const int wbase = ci*72 + g*2;   // ulonglong2 units
      #pragma unroll
      for (int dr = 0; dr < 3; dr++){
        #pragma unroll
        for (int dc = 0; dc < 3; dc++){
          const int k = dr*3 + dc;
          const ulonglong2 wA = sw2[wbase + k*8];
          const ulonglong2 wB = sw2[wbase + k*8 + 1];
          #pragma unroll
          for (int px = 0; px < 4; px++){
            asm("fma.rn.f32x2 %0, %1, %2, %0;" : "+l"(acc[px][0]) : "l"(vd[dr][px+dc]), "l"(wA.x));
            asm("fma.rn.f32x2 %0, %1, %2, %0;" : "+l"(acc[px][1]) : "l"(vd[dr][px+dc]), "l"(wA.y));
            asm("fma.rn.f32x2 %0, %1, %2, %0;" : "+l"(acc[px][2]) : "l"(vd[dr][px+dc]), "l"(wB.x));
            asm("fma.rn.f32x2 %0, %1, %2, %0;" : "+l"(acc[px][3]) : "l"(vd[dr][px+dc]), "l"(wB.y));
          }
        }
      }
    }

    const size_t rc = (size_t)(h0+hh)*WW2 + (w0+w4);
    #pragma unroll
    for (int j = 0; j < 4; j++){
      float4 vlo, vhi;
      float* plo = &vlo.x; float* phi = &vhi.x;
      #pragma unroll
      for (int px = 0; px < 4; px++){
        unsigned lo, hi;
        asm("mov.b64 {%0, %1}, %2;" : "=r"(lo), "=r"(hi) : "l"(acc[px][j]));
        plo[px] = tanhf(__uint_as_float(lo));
        phi[px] = tanhf(__uint_as_float(hi));
      }
      const int co0 = g*8 + j*2;
      #pragma unroll
      for (int h = 0; h < 2; h++){
        const float4 kv = h ? vhi : vlo;
        const size_t po = boff + (size_t)(co0+h)*HWSZ + rc;
        *(float4*)(dst + po) = kv;
        if (EPI == 1){
          const float4 y0v = *(const float4*)(eA[0] + po);
          const float4 k1v = *(const float4*)(eA[1] + po);
          const float4 k3v = *(const float4*)(eA[2] + po);
          const float4 k4v = *(const float4*)(eA[3] + po);
          const float4 k5v = *(const float4*)(eA[4] + po);
          float4 o;
          #pragma unroll
          for (int cmp = 0; cmp < 4; cmp++){
            const float k1 = (&k1v.x)[cmp], k3 = (&k3v.x)[cmp], k4 = (&k4v.x)[cmp];
            const float k5 = (&k5v.x)[cmp], k6 = (&kv.x)[cmp], y0 = (&y0v.x)[cmp];
            float s = fmaf(FCS1, k1, 0.f);
            s = fmaf(FCS3, k3, s); s = fmaf(FCS4, k4, s);
            s = fmaf(FCS5, k5, s); s = fmaf(FCS6, k6, s);
            (&o.x)[cmp] = fmaf(dtv, s, y0);
          }
          *(float4*)(dst2 + po) = o;
        }
        if (EPI == 2){
          const float4 y0v = *(const float4*)(eA[0] + po);
          const float4 y1v = *(const float4*)(eA[1] + po);
          const float4 k1v = *(const float4*)(eA[2] + po);
          const float4 k3v = *(const float4*)(eA[3] + po);
          const float4 k4v = *(const float4*)(eA[4] + po);
          const float4 k5v = *(const float4*)(eA[5] + po);
          const float4 k6v = *(const float4*)(eA[6] + po);
          #pragma unroll
          for (int cmp = 0; cmp < 4; cmp++){
            float e = FCE1 * (&k1v.x)[cmp];
            e = fmaf(FCE3, (&k3v.x)[cmp], e);
            e = fmaf(FCE4, (&k4v.x)[cmp], e);
            e = fmaf(FCE5, (&k5v.x)[cmp], e);
            e = fmaf(FCE6, (&k6v.x)[cmp], e);
            e = fmaf(FCE7, (&kv.x)[cmp],  e);
            e *= dtv;
            const float tol = ATOLF + RTOLF*fmaxf(fabsf((&y0v.x)[cmp]), fabsf((&y1v.x)[cmp]));
            const float r = e / tol;
            errA += (double)r * (double)r;
          }
        }
      }
    }
    __syncthreads();
  }
  if (EPI == 2) red_write(errA, s_red, g_pA);
  gbar(nb);
}

template<int NK>
__device__ void combine(float* __restrict__ dst, const float* __restrict__ base,
                        float dt, const float* const* ks, const float* cf, int nb)
{
  const int gid = blockIdx.x*THREADS + threadIdx.x, nthr = nb*THREADS;
  const float4* b4 = (const float4*)base;
  float4* d4 = (float4*)dst;
  for (int i = gid; i < NTOT/4; i += nthr){
    float4 y = b4[i];
    float sx=0.f, sy=0.f, sz=0.f, sw=0.f;
    #pragma unroll
    for (int j = 0; j < NK; j++){
      float4 k = ((const float4*)ks[j])[i];
      const float c = cf[j];
      sx = fmaf(c,k.x,sx); sy = fmaf(c,k.y,sy); sz = fmaf(c,k.z,sz); sw = fmaf(c,k.w,sw);
    }
    float4 o;
    o.x = fmaf(dt,sx,y.x); o.y = fmaf(dt,sy,y.y); o.z = fmaf(dt,sz,y.z); o.w = fmaf(dt,sw,y.w);
    d4[i] = o;
  }
  gbar(nb);
}

__global__ void __launch_bounds__(THREADS, 2)
odenet_kernel(const float* __restrict__ x, const float* __restrict__ Wconv,
              const float* __restrict__ Wout, const float* __restrict__ bout,
              float* __restrict__ out, int nb)
{
  extern __shared__ char dsm[];
  float* s_w   = (float*)dsm;
  float* s_inp = (float*)(dsm + SW_BYTES);
  double* s_red = (double*)(dsm + SW_BYTES + SIN_BYTES);
  double* s_bc  = s_red + 8;

  const int gid = blockIdx.x*THREADS + threadIdx.x, nthr = nb*THREADS;
  const int tid = threadIdx.x;

  // load + transpose weights into shared: s_w[ci*288 + k*32 + co]
  for (int i = tid; i < CC*CC*9; i += THREADS){
    const int ci = i / 288, rem = i - ci*288;
    const int k = rem >> 5, co = rem & 31;
    s_w[i] = Wconv[(co*CC + ci)*9 + k];
  }
  // pad x: Y0 = concat(x, zeros)
  {
    float* Y = SLOT(0);
    for (int i = gid; i < NTOT; i += nthr){
      const int c = (i >> 14) & 31, b = i >> 19;
      float v = 0.f;
      if (c < 3) v = x[(size_t)(b*3 + c)*HWSZ + (i & (HWSZ-1))];
      Y[i] = v;
    }
  }
  gbar(nb);

  // slot indices: iY0 state, iSc stage scratch, iK1, iY1K2 (K2 early / y1 late), iK7;
  // fixed: K3=4, K4=5, K5=6, K6=7
  int iY0=0, iSc=1, iK1=2, iY1K2=3, iK7=8;

  conv_tanh<0>(SLOT(iY0), SLOT(iK1), 0, 0, 0.f, nb, s_w, s_inp, s_red);   // f0

  // initial step size (Hairer, order 4)
  {
    const float* Y = SLOT(iY0); const float* F = SLOT(iK1);
    double a=0.0, b=0.0;
    for (int i = gid; i < NTOT; i += nthr){
      const float yi = Y[i], fi = F[i];
      const float sc = ATOLF + RTOLF*fabsf(yi);
      const float r0 = yi/sc, r1 = fi/sc;
      a += (double)r0*r0; b += (double)r1*r1;
    }
    red_write(a, s_red, g_pA); red_write(b, s_red, g_pB);
    gbar(nb);
  }
  const float d0 = sqrtf((float)sum_parts(g_pA, nb, s_bc));
  const float d1 = sqrtf((float)sum_parts(g_pB, nb, s_bc));
  const float h0 = (d0 < 1e-5f || d1 < 1e-5f) ? 1e-6f : 0.01f*d0/d1;
  { const float* ks[1] = { SLOT(iK1) }; const float cf[1] = { 1.f };
    combine<1>(SLOT(iSc), SLOT(iY0), h0, ks, cf, nb); }
  conv_tanh<0>(SLOT(iSc), SLOT(iY1K2), 0, 0, 0.f, nb, s_w, s_inp, s_red); // f1
  {
    const float* Y = SLOT(iY0); const float* F0 = SLOT(iK1); const float* F1 = SLOT(iY1K2);
    double a = 0.0;
    for (int i = gid; i < NTOT; i += nthr){
      const float sc = ATOLF + RTOLF*fabsf(Y[i]);
      const float r = (F1[i] - F0[i]) / sc;
      a += (double)r*r;
    }
    red_write(a, s_red, g_pA); gbar(nb);
  }
  const float d2 = sqrtf((float)sum_parts(g_pA, nb, s_bc)) / h0;
  float h1;
  if (d1 <= 1e-15f && d2 <= 1e-15f) h1 = fmaxf(1e-6f, h0*1e-3f);
  else                              h1 = powf(0.01f / fmaxf(d1, d2), 0.2f);
  float dt = fminf(100.f*h0, h1);

  float t = 0.f, last_t = 0.f, dt_used = dt;
  int any = 0, iter = 0;

  while (t < 1.0f && iter < 1000 && dt > 0.f){
    iter++;
    { const float* ks[1] = { SLOT(iK1) }; const float cf[1] = { FB21 };
      combine<1>(SLOT(iSc), SLOT(iY0), dt, ks, cf, nb); }
    conv_tanh<0>(SLOT(iSc), SLOT(iY1K2), 0, 0, 0.f, nb, s_w, s_inp, s_red);      // k2
    { const float* ks[2] = { SLOT(iK1), SLOT(iY1K2) }; const float cf[2] = { FB31, FB32 };
      combine<2>(SLOT(iSc), SLOT(iY0), dt, ks, cf, nb); }
    conv_tanh<0>(SLOT(iSc), SLOT(4), 0, 0, 0.f, nb, s_w, s_inp, s_red);          // k3
    { const float* ks[3] = { SLOT(iK1), SLOT(iY1K2), SLOT(4) };
      const float cf[3] = { FB41, FB42, FB43 };
      combine<3>(SLOT(iSc), SLOT(iY0), dt, ks, cf, nb); }
    conv_tanh<0>(SLOT(iSc), SLOT(5), 0, 0, 0.f, nb, s_w, s_inp, s_red);          // k4
    { const float* ks[4] = { SLOT(iK1), SLOT(iY1K2), SLOT(4), SLOT(5) };
      const float cf[4] = { FB51, FB52, FB53, FB54 };
      combine<4>(SLOT(iSc), SLOT(iY0), dt, ks, cf, nb); }
    conv_tanh<0>(SLOT(iSc), SLOT(6), 0, 0, 0.f, nb, s_w, s_inp, s_red);          // k5
    { const float* ks[5] = { SLOT(iK1), SLOT(iY1K2), SLOT(4), SLOT(5), SLOT(6) };
      const float cf[5] = { FB61, FB62, FB63, FB64, FB65 };
      combine<5>(SLOT(iSc), SLOT(iY0), dt, ks, cf, nb); }
    { const float* eA1[5] = { SLOT(iY0), SLOT(iK1), SLOT(4), SLOT(5), SLOT(6) };
      conv_tanh<1>(SLOT(iSc), SLOT(7), SLOT(iY1K2), eA1, dt, nb, s_w, s_inp, s_red); } // k6 + y1
    { const float* eA2[7] = { SLOT(iY0), SLOT(iY1K2), SLOT(iK1), SLOT(4), SLOT(5), SLOT(6), SLOT(7) };
      conv_tanh<2>(SLOT(iY1K2), SLOT(iK7), 0, eA2, dt, nb, s_w, s_inp, s_red); }       // k7 + err

    const double sum = sum_parts(g_pA, nb, s_bc);
    const float ratio = sqrtf((float)(sum / (double)NTOT));
    const float dfac = (ratio < 1.f) ? 1.0f : 0.2f;
    const float factor = fminf(10.f, fmaxf(0.9f * powf(ratio, -0.2f), dfac));
    const float new_dt = dt * factor;
    if (ratio <= 1.f){
      any = 1; dt_used = dt; last_t = t; t = t + dt;
      if (t >= 1.0f){ dt = new_dt; break; }    // final step: keep buffers unswapped
      int tmp = iY0; iY0 = iY1K2; iY1K2 = tmp;
      tmp = iK1; iK1 = iK7; iK7 = tmp;
    }
    dt = new_dt;
  }

  // interpolate to t=1, fused with global spatial max
  {
    const float xr = any ? (1.0f - last_t) / (t - last_t) : 0.f;
    const float dtu = dt_used;
    const float* Y0 = SLOT(iY0); const float* Y1 = SLOT(iY1K2);
    const float* K1 = SLOT(iK1); const float* K3 = SLOT(4);
    const float* K4 = SLOT(5);   const float* K5 = SLOT(6);
    const float* K6 = SLOT(7);   const float* K7 = SLOT(iK7);
    const int gw = gid >> 5, lane = threadIdx.x & 31, nw = nthr >> 5;
    for (int p = gw; p < BB*CC; p += nw){
      const size_t base = (size_t)p * HWSZ;
      float m = -3.402823466e38f;
      for (int i = lane; i < HWSZ; i += 32){
        const size_t idx = base + i;
        const float y0 = Y0[idx];
        float v = y0;
        if (any){
          const float y1 = Y1[idx];
          const float k1 = K1[idx], k7 = K7[idx];
          float s = FCM1*k1;
          s = fmaf(FCM3, K3[idx], s); s = fmaf(FCM4, K4[idx], s);
          s = fmaf(FCM5, K5[idx], s); s = fmaf(FCM6, K6[idx], s);
          s = fmaf(FCM7, k7, s);
          const float ym = fmaf(dtu, s, y0);
          const float dy0 = k1*dtu, dy1 = k7*dtu;
          const float ca = 2.f*(dy1 - dy0) - 8.f*(y1 + y0) + 16.f*ym;
          const float cb = 5.f*dy0 - 3.f*dy1 + 18.f*y0 + 14.f*y1 - 32.f*ym;
          const float cc = -4.f*dy0 + dy1 - 11.f*y0 - 5.f*y1 + 16.f*ym;
          v = fmaf(fmaf(fmaf(fmaf(ca, xr, cb), xr, cc), xr, dy0), xr, y0);
        }
        m = fmaxf(m, v);
      }
      #pragma unroll
      for (int o = 16; o; o >>= 1) m = fmaxf(m, __shfl_down_sync(0xffffffffu, m, o));
      if (lane == 0) g_feats[p] = m;
    }
    gbar(nb);
  }

  // linear head: out[b][n] = feats[b] . Wout[n] + bout[n]
  for (int idx = gid; idx < BB*1000; idx += nthr){
    const int b = idx / 1000, n = idx - b*1000;
    const float* f = g_feats + b*CC;
    const float* w = Wout + n*CC;
    float s = bout[n];
    #pragma unroll
    for (int c = 0; c < CC; c++) s = fmaf(f[c], __ldg(w + c), s);
    out[idx] = s;
  }
}

extern "C" void kernel_launch(void* const* d_in, const int* in_sizes, int n_in,
                              void* d_out, int out_size)
{
  const float* x     = (const float*)d_in[0];
  const float* Wconv = (const float*)d_in[1];
  const float* Wout  = (const float*)d_in[2];
  const float* bout  = (const float*)d_in[3];
  float* out = (float*)d_out;

  cudaFuncSetAttribute(odenet_kernel, cudaFuncAttributeMaxDynamicSharedMemorySize, DSM_BYTES);

  int dev = 0; cudaGetDevice(&dev);
  int smCount = 0;
  cudaDeviceGetAttribute(&smCount, cudaDevAttrMultiProcessorCount, dev);
  int bpm = 0;
  cudaOccupancyMaxActiveBlocksPerMultiprocessor(&bpm, odenet_kernel, THREADS, DSM_BYTES);
  if (bpm < 1) bpm = 1;
  int nb = smCount * bpm;
  if (nb > NB_MAX) nb = NB_MAX;
  if (nb < 1) nb = 1;

  odenet_kernel<<<nb, THREADS, DSM_BYTES>>>(x, Wconv, Wout, bout, out, nb);
}

// round 11
// speedup vs baseline: 1.3179x; 1.0002x over previous
#include <cuda_runtime.h>
#include <math.h>
#include <stdint.h>

#define THREADS 256
#define BB 32
#define CC 32
#define HH 128
#define WW2 128
#define HWSZ (HH*WW2)
#define CHWSZ (CC*HWSZ)
#define NTOT (BB*CHWSZ)
#define NB_MAX 2048
#define RTOLF 1e-3f
#define ATOLF 1e-3f

// dynamic smem: weights (36864B) + padded input tile 32x18x20 (46080B) + reduction
#define SW_BYTES   (CC*9*CC*4)
#define SIN_BYTES  (CC*18*20*4)
#define DSM_BYTES  (SW_BYTES + SIN_BYTES + 128)

// dopri5 tableau (f32)
#define FB21 ((float)(1.0/5.0))
#define FB31 ((float)(3.0/40.0))
#define FB32 ((float)(9.0/40.0))
#define FB41 ((float)(44.0/45.0))
#define FB42 ((float)(-56.0/15.0))
#define FB43 ((float)(32.0/9.0))
#define FB51 ((float)(19372.0/6561.0))
#define FB52 ((float)(-25360.0/2187.0))
#define FB53 ((float)(64448.0/6561.0))
#define FB54 ((float)(-212.0/729.0))
#define FB61 ((float)(9017.0/3168.0))
#define FB62 ((float)(-355.0/33.0))
#define FB63 ((float)(46732.0/5247.0))
#define FB64 ((float)(49.0/176.0))
#define FB65 ((float)(-5103.0/18656.0))
#define FCS1 ((float)(35.0/384.0))
#define FCS3 ((float)(500.0/1113.0))
#define FCS4 ((float)(125.0/192.0))
#define FCS5 ((float)(-2187.0/6784.0))
#define FCS6 ((float)(11.0/84.0))
#define FCE1 ((float)(35.0/384.0 - 1951.0/21600.0))
#define FCE3 ((float)(500.0/1113.0 - 22642.0/50085.0))
#define FCE4 ((float)(125.0/192.0 - 451.0/720.0))
#define FCE5 ((float)(-2187.0/6784.0 + 12231.0/42400.0))
#define FCE6 ((float)(11.0/84.0 - 649.0/6300.0))
#define FCE7 ((float)(-1.0/60.0))
#define FCM1 ((float)(6025192743.0/30085553152.0/2.0))
#define FCM3 ((float)(51252292925.0/65400821598.0/2.0))
#define FCM4 ((float)(-2691868925.0/45128329728.0/2.0))
#define FCM5 ((float)(187940372067.0/1594534317056.0/2.0))
#define FCM6 ((float)(-1776094331.0/19743644256.0/2.0))
#define FCM7 ((float)(11237099.0/235043384.0/2.0))

// scratch slots (indices are dynamic; 9 buffers total)
__device__ float  g_mem[(size_t)9 * NTOT];
__device__ double g_pA[NB_MAX];
__device__ double g_pB[NB_MAX];
__device__ float  g_feats[BB*CC];
__device__ unsigned          g_cnt = 0;
__device__ volatile unsigned g_gen = 0;

__device__ __forceinline__ float* SLOT(int s){ return g_mem + (size_t)s * NTOT; }

__device__ __forceinline__ void gbar(int nb){
  __syncthreads();
  if (threadIdx.x == 0){
    unsigned gen = g_gen;
    __threadfence();
    if (atomicAdd(&g_cnt, 1u) == (unsigned)(nb - 1)){
      g_cnt = 0u; __threadfence(); g_gen = gen + 1u;
    } else {
      while (g_gen == gen) { __nanosleep(64); }
      __threadfence();
    }
  }
  __syncthreads();
}

__device__ __forceinline__ void red_write(double v, double* s_red, double* part){
  const int lane = threadIdx.x & 31, w = threadIdx.x >> 5;
  #pragma unroll
  for (int o = 16; o; o >>= 1) v += __shfl_down_sync(0xffffffffu, v, o);
  if (lane == 0) s_red[w] = v;
  __syncthreads();
  if (threadIdx.x == 0){
    double s = 0.0;
    #pragma unroll
    for (int i = 0; i < THREADS/32; i++) s += s_red[i];
    part[blockIdx.x] = s;
  }
  __syncthreads();
}

__device__ __forceinline__ double sum_parts(const double* part, int nb, double* s_bc){
  __syncthreads();
  if (threadIdx.x == 0){
    double s = 0.0;
    for (int i = 0; i < nb; i++) s += part[i];
    *s_bc = s;
  }
  __syncthreads();
  double r = *s_bc;
  __syncthreads();
  return r;
}

// dst = tanh(conv3x3_same(src)); 1 row x 4 px x 8 co per thread.
// EPI=0: plain. EPI=1: also y1 = eA0 + dt*(FCS1*eA1+FCS3*eA2+FCS4*eA3+FCS5*eA4+FCS6*k6) -> dst2.
// EPI=2: also accumulate dopri error ratio^2 (eA = {Y0,Y1,K1,K3,K4,K5,K6}; K7 = local).
template<int EPI>
__device__ void conv_tanh(const float* __restrict__ src, float* __restrict__ dst,
                          float* __restrict__ dst2, const float* const* eA, float dtv,
                          int nb, const float* __restrict__ s_w,
                          float* __restrict__ s_inp, double* s_red)
{
  const int tid = threadIdx.x;
  const int g   = tid & 3;          // 8-channel group
  const int pg  = tid >> 2;         // 0..63
  const int hh  = pg >> 2;          // 0..15
  const int w4  = (pg & 3) << 2;    // 0,4,8,12
  const ulonglong2* sw2 = (const ulonglong2*)s_w;
  const int ntiles = BB * 64;
  double errA = 0.0;
  for (int tile = blockIdx.x; tile < ntiles; tile += nb){
    const int b = tile >> 6, th = (tile >> 3) & 7, tw = tile & 7;
    const int h0 = th*16, w0 = tw*16;
    const size_t boff = (size_t)b * CHWSZ;
    for (int i = tid; i < CC*324; i += THREADS){
      const int ci = i / 324, rem = i - ci*324;
      const int r = rem / 18, c = rem - r*18;
      const int hy = h0 + r - 1, wx = w0 + c - 1;
      float v = 0.f;
      if (hy >= 0 && hy < HH && wx >= 0 && wx < WW2)
        v = src[boff + (size_t)ci*HWSZ + hy*WW2 + wx];
      s_inp[ci*360 + r*20 + c] = v;
    }
    __syncthreads();

    unsigned long long acc[4][4];
    #pragma unroll
    for (int px = 0; px < 4; px++)
      #pragma unroll
      for (int j = 0; j < 4; j++) acc[px][j] = 0ULL;

    #pragma unroll 1
    for (int ci = 0; ci < CC; ci++){
      const float* rowp = s_inp + ci*360 + hh*20 + w4;
      unsigned long long vd[3][6];
      #pragma unroll
      for (int dr = 0; dr < 3; dr++){
        const float4 a  = *(const float4*)(rowp + dr*20);
        const float2 b2 = *(const float2*)(rowp + dr*20 + 4);
        const unsigned u0 = __float_as_uint(a.x),  u1 = __float_as_uint(a.y);
        const unsigned u2 = __float_as_uint(a.z),  u3 = __float_as_uint(a.w);
        const unsigned u4 = __float_as_uint(b2.x), u5 = __float_as_uint(b2.y);
        asm("mov.b64 %0, {%1, %1};" : "=l"(vd[dr][0]) : "r"(u0));
        asm("mov.b64 %0, {%1, %1};" : "=l"(vd[dr][1]) : "r"(u1));
        asm("mov.b64 %0, {%1, %1};" : "=l"(vd[dr][2]) : "r"(u2));
        asm("mov.b64 %0, {%1, %1};" : "=l"(vd[dr][3]) : "r"(u3));
        asm("mov.b64 %0, {%1, %1};" : "=l"(vd[dr][4]) : "r"(u4));
        asm("mov.b64 %0, {%1, %1};" : "=l"(vd[dr][5]) : "r"(u5));
      }
      const int wbase = ci*72 + g*2;   // ulonglong2 units
      #pragma unroll
      for (int dr = 0; dr < 3; dr++){
        #pragma unroll
        for (int dc = 0; dc < 3; dc++){
          const int k = dr*3 + dc;
          const ulonglong2 wA = sw2[wbase + k*8];
          const ulonglong2 wB = sw2[wbase + k*8 + 1];
          #pragma unroll
          for (int px = 0; px < 4; px++){
            asm("fma.rn.f32x2 %0, %1, %2, %0;" : "+l"(acc[px][0]) : "l"(vd[dr][px+dc]), "l"(wA.x));
            asm("fma.rn.f32x2 %0, %1, %2, %0;" : "+l"(acc[px][1]) : "l"(vd[dr][px+dc]), "l"(wA.y));
            asm("fma.rn.f32x2 %0, %1, %2, %0;" : "+l"(acc[px][2]) : "l"(vd[dr][px+dc]), "l"(wB.x));
            asm("fma.rn.f32x2 %0, %1, %2, %0;" : "+l"(acc[px][3]) : "l"(vd[dr][px+dc]), "l"(wB.y));
          }
        }
      }
    }

    const size_t rc = (size_t)(h0+hh)*WW2 + (w0+w4);
    #pragma unroll
    for (int j = 0; j < 4; j++){
      float4 vlo, vhi;
      float* plo = &vlo.x; float* phi = &vhi.x;
      #pragma unroll
      for (int px = 0; px < 4; px++){
        unsigned lo, hi;
        asm("mov.b64 {%0, %1}, %2;" : "=r"(lo), "=r"(hi) : "l"(acc[px][j]));
        plo[px] = tanhf(__uint_as_float(lo));
        phi[px] = tanhf(__uint_as_float(hi));
      }
      const int co0 = g*8 + j*2;
      #pragma unroll
      for (int h = 0; h < 2; h++){
        const float4 kv = h ? vhi : vlo;
        const size_t po = boff + (size_t)(co0+h)*HWSZ + rc;
        *(float4*)(dst + po) = kv;
        if (EPI == 1){
          const float4 y0v = *(const float4*)(eA[0] + po);
          const float4 k1v = *(const float4*)(eA[1] + po);
          const float4 k3v = *(const float4*)(eA[2] + po);
          const float4 k4v = *(const float4*)(eA[3] + po);
          const float4 k5v = *(const float4*)(eA[4] + po);
          float4 o;
          #pragma unroll
          for (int cmp = 0; cmp < 4; cmp++){
            const float k1 = (&k1v.x)[cmp], k3 = (&k3v.x)[cmp], k4 = (&k4v.x)[cmp];
            const float k5 = (&k5v.x)[cmp], k6 = (&kv.x)[cmp], y0 = (&y0v.x)[cmp];
            float s = fmaf(FCS1, k1, 0.f);
            s = fmaf(FCS3, k3, s); s = fmaf(FCS4, k4, s);
            s = fmaf(FCS5, k5, s); s = fmaf(FCS6, k6, s);
            (&o.x)[cmp] = fmaf(dtv, s, y0);
          }
          *(float4*)(dst2 + po) = o;
        }
        if (EPI == 2){
          const float4 y0v = *(const float4*)(eA[0] + po);
          const float4 y1v = *(const float4*)(eA[1] + po);
          const float4 k1v = *(const float4*)(eA[2] + po);
          const float4 k3v = *(const float4*)(eA[3] + po);
          const float4 k4v = *(const float4*)(eA[4] + po);
          const float4 k5v = *(const float4*)(eA[5] + po);
          const float4 k6v = *(const float4*)(eA[6] + po);
          #pragma unroll
          for (int cmp = 0; cmp < 4; cmp++){
            float e = FCE1 * (&k1v.x)[cmp];
            e = fmaf(FCE3, (&k3v.x)[cmp], e);
            e = fmaf(FCE4, (&k4v.x)[cmp], e);
            e = fmaf(FCE5, (&k5v.x)[cmp], e);
            e = fmaf(FCE6, (&k6v.x)[cmp], e);
            e = fmaf(FCE7, (&kv.x)[cmp],  e);
            e *= dtv;
            const float tol = ATOLF + RTOLF*fmaxf(fabsf((&y0v.x)[cmp]), fabsf((&y1v.x)[cmp]));
            const float r = e / tol;
            errA += (double)r * (double)r;
          }
        }
      }
    }
    __syncthreads();
  }
  if (EPI == 2) red_write(errA, s_red, g_pA);
  gbar(nb);
}

template<int NK>
__device__ void combine(float* __restrict__ dst, const float* __restrict__ base,
                        float dt, const float* const* ks, const float* cf, int nb)
{
  const int gid = blockIdx.x*THREADS + threadIdx.x, nthr = nb*THREADS;
  const float4* b4 = (const float4*)base;
  float4* d4 = (float4*)dst;
  for (int i = gid; i < NTOT/4; i += nthr){
    float4 y = b4[i];
    float sx=0.f, sy=0.f, sz=0.f, sw=0.f;
    #pragma unroll
    for (int j = 0; j < NK; j++){
      float4 k = ((const float4*)ks[j])[i];
      const float c = cf[j];
      sx = fmaf(c,k.x,sx); sy = fmaf(c,k.y,sy); sz = fmaf(c,k.z,sz); sw = fmaf(c,k.w,sw);
    }
    float4 o;
    o.x = fmaf(dt,sx,y.x); o.y = fmaf(dt,sy,y.y); o.z = fmaf(dt,sz,y.z); o.w = fmaf(dt,sw,y.w);
    d4[i] = o;
  }
  gbar(nb);
}

__global__ void __launch_bounds__(THREADS, 2)
odenet_kernel(const float* __restrict__ x, const float* __restrict__ Wconv,
              const float* __restrict__ Wout, const float* __restrict__ bout,
              float* __restrict__ out, int nb)
{
  extern __shared__ char dsm[];
  float* s_w   = (float*)dsm;
  float* s_inp = (float*)(dsm + SW_BYTES);
  double* s_red = (double*)(dsm + SW_BYTES + SIN_BYTES);
  double* s_bc  = s_red + 8;

  const int gid = blockIdx.x*THREADS + threadIdx.x, nthr = nb*THREADS;
  const int tid = threadIdx.x;

  // load + transpose weights into shared: s_w[ci*288 + k*32 + co]
  for (int i = tid; i < CC*CC*9; i += THREADS){
    const int ci = i / 288, rem = i - ci*288;
    const int k = rem >> 5, co = rem & 31;
    s_w[i] = Wconv[(co*CC + ci)*9 + k];
  }
  // pad x: Y0 = concat(x, zeros)
  {
    float* Y = SLOT(0);
    for (int i = gid; i < NTOT; i += nthr){
      const int c = (i >> 14) & 31, b = i >> 19;
      float v = 0.f;
      if (c < 3) v = x[(size_t)(b*3 + c)*HWSZ + (i & (HWSZ-1))];
      Y[i] = v;
    }
  }
  gbar(nb);

  // slot indices: iY0 state, iSc stage scratch, iK1, iY1K2 (K2 early / y1 late), iK7;
  // fixed: K3=4, K4=5, K5=6, K6=7
  int iY0=0, iSc=1, iK1=2, iY1K2=3, iK7=8;

  conv_tanh<0>(SLOT(iY0), SLOT(iK1), 0, 0, 0.f, nb, s_w, s_inp, s_red);   // f0

  // initial step size (Hairer, order 4)
  {
    const float* Y = SLOT(iY0); const float* F = SLOT(iK1);
    double a=0.0, b=0.0;
    for (int i = gid; i < NTOT; i += nthr){
      const float yi = Y[i], fi = F[i];
      const float sc = ATOLF + RTOLF*fabsf(yi);
      const float r0 = yi/sc, r1 = fi/sc;
      a += (double)r0*r0; b += (double)r1*r1;
    }
    red_write(a, s_red, g_pA); red_write(b, s_red, g_pB);
    gbar(nb);
  }
  const float d0 = sqrtf((float)sum_parts(g_pA, nb, s_bc));
  const float d1 = sqrtf((float)sum_parts(g_pB, nb, s_bc));
  const float h0 = (d0 < 1e-5f || d1 < 1e-5f) ? 1e-6f : 0.01f*d0/d1;
  { const float* ks[1] = { SLOT(iK1) }; const float cf[1] = { 1.f };
    combine<1>(SLOT(iSc), SLOT(iY0), h0, ks, cf, nb); }
  conv_tanh<0>(SLOT(iSc), SLOT(iY1K2), 0, 0, 0.f, nb, s_w, s_inp, s_red); // f1
  {
    const float* Y = SLOT(iY0); const float* F0 = SLOT(iK1); const float* F1 = SLOT(iY1K2);
    double a = 0.0;
    for (int i = gid; i < NTOT; i += nthr){
      const float sc = ATOLF + RTOLF*fabsf(Y[i]);
      const float r = (F1[i] - F0[i]) / sc;
      a += (double)r*r;
    }
    red_write(a, s_red, g_pA); gbar(nb);
  }
  const float d2 = sqrtf((float)sum_parts(g_pA, nb, s_bc)) / h0;
  float h1;
  if (d1 <= 1e-15f && d2 <= 1e-15f) h1 = fmaxf(1e-6f, h0*1e-3f);
  else                              h1 = powf(0.01f / fmaxf(d1, d2), 0.2f);
  float dt = fminf(100.f*h0, h1);

  float t = 0.f, last_t = 0.f, dt_used = dt;
  int any = 0, iter = 0;

  while (t < 1.0f && iter < 1000 && dt > 0.f){
    iter++;
    { const float* ks[1] = { SLOT(iK1) }; const float cf[1] = { FB21 };
      combine<1>(SLOT(iSc), SLOT(iY0), dt, ks, cf, nb); }
    conv_tanh<0>(SLOT(iSc), SLOT(iY1K2), 0, 0, 0.f, nb, s_w, s_inp, s_red);      // k2
    { const float* ks[2] = { SLOT(iK1), SLOT(iY1K2) }; const float cf[2] = { FB31, FB32 };
      combine<2>(SLOT(iSc), SLOT(iY0), dt, ks, cf, nb); }
    conv_tanh<0>(SLOT(iSc), SLOT(4), 0, 0, 0.f, nb, s_w, s_inp, s_red);          // k3
    { const float* ks[3] = { SLOT(iK1), SLOT(iY1K2), SLOT(4) };
      const float cf[3] = { FB41, FB42, FB43 };
      combine<3>(SLOT(iSc), SLOT(iY0), dt, ks, cf, nb); }
    conv_tanh<0>(SLOT(iSc), SLOT(5), 0, 0, 0.f, nb, s_w, s_inp, s_red);          // k4
    { const float* ks[4] = { SLOT(iK1), SLOT(iY1K2), SLOT(4), SLOT(5) };
      const float cf[4] = { FB51, FB52, FB53, FB54 };
      combine<4>(SLOT(iSc), SLOT(iY0), dt, ks, cf, nb); }
    conv_tanh<0>(SLOT(iSc), SLOT(6), 0, 0, 0.f, nb, s_w, s_inp, s_red);          // k5
    { const float* ks[5] = { SLOT(iK1), SLOT(iY1K2), SLOT(4), SLOT(5), SLOT(6) };
      const float cf[5] = { FB61, FB62, FB63, FB64, FB65 };
      combine<5>(SLOT(iSc), SLOT(iY0), dt, ks, cf, nb); }
    { const float* eA1[5] = { SLOT(iY0), SLOT(iK1), SLOT(4), SLOT(5), SLOT(6) };
      conv_tanh<1>(SLOT(iSc), SLOT(7), SLOT(iY1K2), eA1, dt, nb, s_w, s_inp, s_red); } // k6 + y1
    { const float* eA2[7] = { SLOT(iY0), SLOT(iY1K2), SLOT(iK1), SLOT(4), SLOT(5), SLOT(6), SLOT(7) };
      conv_tanh<2>(SLOT(iY1K2), SLOT(iK7), 0, eA2, dt, nb, s_w, s_inp, s_red); }       // k7 + err

    const double sum = sum_parts(g_pA, nb, s_bc);
    const float ratio = sqrtf((float)(sum / (double)NTOT));
    const float dfac = (ratio < 1.f) ? 1.0f : 0.2f;
    const float factor = fminf(10.f, fmaxf(0.9f * powf(ratio, -0.2f), dfac));
    const float new_dt = dt * factor;
    if (ratio <= 1.f){
      any = 1; dt_used = dt; last_t = t; t = t + dt;
      if (t >= 1.0f){ dt = new_dt; break; }    // final step: keep buffers unswapped
      int tmp = iY0; iY0 = iY1K2; iY1K2 = tmp;
      tmp = iK1; iK1 = iK7; iK7 = tmp;
    }
    dt = new_dt;
  }

  // interpolate to t=1, fused with global spatial max
  {
    const float xr = any ? (1.0f - last_t) / (t - last_t) : 0.f;
    const float dtu = dt_used;
    const float* Y0 = SLOT(iY0); const float* Y1 = SLOT(iY1K2);
    const float* K1 = SLOT(iK1); const float* K3 = SLOT(4);
    const float* K4 = SLOT(5);   const float* K5 = SLOT(6);
    const float* K6 = SLOT(7);   const float* K7 = SLOT(iK7);
    const int gw = gid >> 5, lane = threadIdx.x & 31, nw = nthr >> 5;
    for (int p = gw; p < BB*CC; p += nw){
      const size_t base = (size_t)p * HWSZ;
      float m = -3.402823466e38f;
      for (int i = lane; i < HWSZ; i += 32){
        const size_t idx = base + i;
        const float y0 = Y0[idx];
        float v = y0;
        if (any){
          const float y1 = Y1[idx];
          const float k1 = K1[idx], k7 = K7[idx];
          float s = FCM1*k1;
          s = fmaf(FCM3, K3[idx], s); s = fmaf(FCM4, K4[idx], s);
          s = fmaf(FCM5, K5[idx], s); s = fmaf(FCM6, K6[idx], s);
          s = fmaf(FCM7, k7, s);
          const float ym = fmaf(dtu, s, y0);
          const float dy0 = k1*dtu, dy1 = k7*dtu;
          const float ca = 2.f*(dy1 - dy0) - 8.f*(y1 + y0) + 16.f*ym;
          const float cb = 5.f*dy0 - 3.f*dy1 + 18.f*y0 + 14.f*y1 - 32.f*ym;
          const float cc = -4.f*dy0 + dy1 - 11.f*y0 - 5.f*y1 + 16.f*ym;
          v = fmaf(fmaf(fmaf(fmaf(ca, xr, cb), xr, cc), xr, dy0), xr, y0);
        }
        m = fmaxf(m, v);
      }
      #pragma unroll
      for (int o = 16; o; o >>= 1) m = fmaxf(m, __shfl_down_sync(0xffffffffu, m, o));
      if (lane == 0) g_feats[p] = m;
    }
    gbar(nb);
  }

  // linear head: out[b][n] = feats[b] . Wout[n] + bout[n]
  for (int idx = gid; idx < BB*1000; idx += nthr){
    const int b = idx / 1000, n = idx - b*1000;
    const float* f = g_feats + b*CC;
    const float* w = Wout + n*CC;
    float s = bout[n];
    #pragma unroll
    for (int c = 0; c < CC; c++) s = fmaf(f[c], __ldg(w + c), s);
    out[idx] = s;
  }
}

extern "C" void kernel_launch(void* const* d_in, const int* in_sizes, int n_in,
                              void* d_out, int out_size)
{
  const float* x     = (const float*)d_in[0];
  const float* Wconv = (const float*)d_in[1];
  const float* Wout  = (const float*)d_in[2];
  const float* bout  = (const float*)d_in[3];
  float* out = (float*)d_out;

  cudaFuncSetAttribute(odenet_kernel, cudaFuncAttributeMaxDynamicSharedMemorySize, DSM_BYTES);

  int dev = 0; cudaGetDevice(&dev);
  int smCount = 0;
  cudaDeviceGetAttribute(&smCount, cudaDevAttrMultiProcessorCount, dev);
  int bpm = 0;
  cudaOccupancyMaxActiveBlocksPerMultiprocessor(&bpm, odenet_kernel, THREADS, DSM_BYTES);
  if (bpm < 1) bpm = 1;
  int nb = smCount * bpm;
  if (nb > NB_MAX) nb = NB_MAX;
  if (nb < 1) nb = 1;

  odenet_kernel<<<nb, THREADS, DSM_BYTES>>>(x, Wconv, Wout, bout, out, nb);
}

// round 13
// speedup vs baseline: 1.3670x; 1.0373x over previous
#include <cuda_runtime.h>
#include <math.h>
#include <stdint.h>

#define THREADS 256
#define BB 32
#define CC 32
#define HH 128
#define WW2 128
#define HWSZ (HH*WW2)
#define CHWSZ (CC*HWSZ)
#define NTOT (BB*CHWSZ)
#define NB_MAX 2048
#define RTOLF 1e-3f
#define ATOLF 1e-3f

#define SW_BYTES   (CC*9*CC*4)
#define SIN_BYTES  (CC*18*20*4)
#define DSM_BYTES  (SW_BYTES + SIN_BYTES + 128)

#define FB21 ((float)(1.0/5.0))
#define FB31 ((float)(3.0/40.0))
#define FB32 ((float)(9.0/40.0))
#define FB41 ((float)(44.0/45.0))
#define FB42 ((float)(-56.0/15.0))
#define FB43 ((float)(32.0/9.0))
#define FB51 ((float)(19372.0/6561.0))
#define FB52 ((float)(-25360.0/2187.0))
#define FB53 ((float)(64448.0/6561.0))
#define FB54 ((float)(-212.0/729.0))
#define FB61 ((float)(9017.0/3168.0))
#define FB62 ((float)(-355.0/33.0))
#define FB63 ((float)(46732.0/5247.0))
#define FB64 ((float)(49.0/176.0))
#define FB65 ((float)(-5103.0/18656.0))
#define FCS1 ((float)(35.0/384.0))
#define FCS3 ((float)(500.0/1113.0))
#define FCS4 ((float)(125.0/192.0))
#define FCS5 ((float)(-2187.0/6784.0))
#define FCS6 ((float)(11.0/84.0))
#define FCE1 ((float)(35.0/384.0 - 1951.0/21600.0))
#define FCE3 ((float)(500.0/1113.0 - 22642.0/50085.0))
#define FCE4 ((float)(125.0/192.0 - 451.0/720.0))
#define FCE5 ((float)(-2187.0/6784.0 + 12231.0/42400.0))
#define FCE6 ((float)(11.0/84.0 - 649.0/6300.0))
#define FCE7 ((float)(-1.0/60.0))
#define FCM1 ((float)(6025192743.0/30085553152.0/2.0))
#define FCM3 ((float)(51252292925.0/65400821598.0/2.0))
#define FCM4 ((float)(-2691868925.0/45128329728.0/2.0))
#define FCM5 ((float)(187940372067.0/1594534317056.0/2.0))
#define FCM6 ((float)(-1776094331.0/19743644256.0/2.0))
#define FCM7 ((float)(11237099.0/235043384.0/2.0))

// 10 scratch slots (two stage-scratch buffers for ping-pong)
__device__ float  g_mem[(size_t)10 * NTOT];
__device__ double g_pA[NB_MAX];
__device__ double g_pB[NB_MAX];
__device__ float  g_feats[BB*CC];
__device__ unsigned          g_cnt = 0;
__device__ volatile unsigned g_gen = 0;

__device__ __forceinline__ float* SLOT(int s){ return g_mem + (size_t)s * NTOT; }

__device__ __forceinline__ void gbar(int nb){
  __syncthreads();
  if (threadIdx.x == 0){
    unsigned gen = g_gen;
    __threadfence();
    if (atomicAdd(&g_cnt, 1u) == (unsigned)(nb - 1)){
      g_cnt = 0u; __threadfence(); g_gen = gen + 1u;
    } else {
      while (g_gen == gen) { __nanosleep(64); }
      __threadfence();
    }
  }
  __syncthreads();
}

__device__ __forceinline__ void red_write(double v, double* s_red, double* part){
  const int lane = threadIdx.x & 31, w = threadIdx.x >> 5;
  #pragma unroll
  for (int o = 16; o; o >>= 1) v += __shfl_down_sync(0xffffffffu, v, o);
  if (lane == 0) s_red[w] = v;
  __syncthreads();
  if (threadIdx.x == 0){
    double s = 0.0;
    #pragma unroll
    for (int i = 0; i < THREADS/32; i++) s += s_red[i];
    part[blockIdx.x] = s;
  }
  __syncthreads();
}

__device__ __forceinline__ double sum_parts(const double* part, int nb, double* s_bc){
  __syncthreads();
  if (threadIdx.x == 0){
    double s = 0.0;
    for (int i = 0; i < nb; i++) s += part[i];
    *s_bc = s;
  }
  __syncthreads();
  double r = *s_bc;
  __syncthreads();
  return r;
}

// dst = tanh(conv3x3_same(src)); 1 row x 4 px x 8 co per thread.
// MODE 0: plain.
// MODE 1: fused stage-combine: dst2 = eA[0] + dtv*(sum_{j<NC-1} cf[j]*eA[j+1] + cf[NC-1]*k_local)
// MODE 2: fused error ratio^2 (eA = {Y0,Y1,K1,K3,K4,K5,K6}; K7 = local).
template<int MODE, int NC>
__device__ void conv_tanh(const float* __restrict__ src, float* __restrict__ dst,
                          float* __restrict__ dst2, const float* const* eA,
                          const float* cf, float dtv,
                          int nb, const float* __restrict__ s_w,
                          float* __restrict__ s_inp, double* s_red)
{
  const int tid = threadIdx.x;
  const int g   = tid & 3;
  const int pg  = tid >> 2;
  const int hh  = pg >> 2;
  const int w4  = (pg & 3) << 2;
  const ulonglong2* sw2 = (const ulonglong2*)s_w;
  const int ntiles = BB * 64;
  double errA = 0.0;
  for (int tile = blockIdx.x; tile < ntiles; tile += nb){
    const int b = tile >> 6, th = (tile >> 3) & 7, tw = tile & 7;
    const int h0 = th*16, w0 = tw*16;
    const size_t boff = (size_t)b * CHWSZ;
    for (int i = tid; i < CC*324; i += THREADS){
      const int ci = i / 324, rem = i - ci*324;
      const int r = rem / 18, c = rem - r*18;
      const int hy = h0 + r - 1, wx = w0 + c - 1;
      float v = 0.f;
      if (hy >= 0 && hy < HH && wx >= 0 && wx < WW2)
        v = src[boff + (size_t)ci*HWSZ + hy*WW2 + wx];
      s_inp[ci*360 + r*20 + c] = v;
    }
    __syncthreads();

    unsigned long long acc[4][4];
    #pragma unroll
    for (int px = 0; px < 4; px++)
      #pragma unroll
      for (int j = 0; j < 4; j++) acc[px][j] = 0ULL;

    #pragma unroll 1
    for (int ci = 0; ci < CC; ci++){
      const float* rowp = s_inp + ci*360 + hh*20 + w4;
      unsigned long long vd[3][6];
      #pragma unroll
      for (int dr = 0; dr < 3; dr++){
        const float4 a  = *(const float4*)(rowp + dr*20);
        const float2 b2 = *(const float2*)(rowp + dr*20 + 4);
        const unsigned u0 = __float_as_uint(a.x),  u1 = __float_as_uint(a.y);
        const unsigned u2 = __float_as_uint(a.z),  u3 = __float_as_uint(a.w);
        const unsigned u4 = __float_as_uint(b2.x), u5 = __float_as_uint(b2.y);
        asm("mov.b64 %0, {%1, %1};" : "=l"(vd[dr][0]) : "r"(u0));
        asm("mov.b64 %0, {%1, %1};" : "=l"(vd[dr][1]) : "r"(u1));
        asm("mov.b64 %0, {%1, %1};" : "=l"(vd[dr][2]) : "r"(u2));
        asm("mov.b64 %0, {%1, %1};" : "=l"(vd[dr][3]) : "r"(u3));
        asm("mov.b64 %0, {%1, %1};" : "=l"(vd[dr][4]) : "r"(u4));
        asm("mov.b64 %0, {%1, %1};" : "=l"(vd[dr][5]) : "r"(u5));
      }
      const int wbase = ci*72 + g*2;
      #pragma unroll
      for (int dr = 0; dr < 3; dr++){
        #pragma unroll
        for (int dc = 0; dc < 3; dc++){
          const int k = dr*3 + dc;
          const ulonglong2 wA = sw2[wbase + k*8];
          const ulonglong2 wB = sw2[wbase + k*8 + 1];
          #pragma unroll
          for (int px = 0; px < 4; px++){
            asm("fma.rn.f32x2 %0, %1, %2, %0;" : "+l"(acc[px][0]) : "l"(vd[dr][px+dc]), "l"(wA.x));
            asm("fma.rn.f32x2 %0, %1, %2, %0;" : "+l"(acc[px][1]) : "l"(vd[dr][px+dc]), "l"(wA.y));
            asm("fma.rn.f32x2 %0, %1, %2, %0;" : "+l"(acc[px][2]) : "l"(vd[dr][px+dc]), "l"(wB.x));
            asm("fma.rn.f32x2 %0, %1, %2, %0;" : "+l"(acc[px][3]) : "l"(vd[dr][px+dc]), "l"(wB.y));
          }
        }
      }
    }

    const size_t rc = (size_t)(h0+hh)*WW2 + (w0+w4);
    #pragma unroll
    for (int j = 0; j < 4; j++){
      float4 vlo, vhi;
      float* plo = &vlo.x; float* phi = &vhi.x;
      #pragma unroll
      for (int px = 0; px < 4; px++){
        unsigned lo, hi;
        asm("mov.b64 {%0, %1}, %2;" : "=r"(lo), "=r"(hi) : "l"(acc[px][j]));
        plo[px] = tanhf(__uint_as_float(lo));
        phi[px] = tanhf(__uint_as_float(hi));
      }
      const int co0 = g*8 + j*2;
      #pragma unroll
      for (int h = 0; h < 2; h++){
        const float4 kv = h ? vhi : vlo;
        const size_t po = boff + (size_t)(co0+h)*HWSZ + rc;
        *(float4*)(dst + po) = kv;
        if (MODE == 1){
          const float4 y0v = *(const float4*)(eA[0] + po);
          float4 kj[(NC > 1) ? (NC - 1) : 1];
          #pragma unroll
          for (int q = 0; q < NC-1; q++) kj[q] = *(const float4*)(eA[q+1] + po);
          float4 o;
          #pragma unroll
          for (int cmp = 0; cmp < 4; cmp++){
            float s = 0.f;
            #pragma unroll
            for (int q = 0; q < NC-1; q++) s = fmaf(cf[q], (&kj[q].x)[cmp], s);
            s = fmaf(cf[NC-1], (&kv.x)[cmp], s);
            (&o.x)[cmp] = fmaf(dtv, s, (&y0v.x)[cmp]);
          }
          *(float4*)(dst2 + po) = o;
        }
        if (MODE == 2){
          const float4 y0v = *(const float4*)(eA[0] + po);
          const float4 y1v = *(const float4*)(eA[1] + po);
          const float4 k1v = *(const float4*)(eA[2] + po);
          const float4 k3v = *(const float4*)(eA[3] + po);
          const float4 k4v = *(const float4*)(eA[4] + po);
          const float4 k5v = *(const float4*)(eA[5] + po);
          const float4 k6v = *(const float4*)(eA[6] + po);
          #pragma unroll
          for (int cmp = 0; cmp < 4; cmp++){
            float e = FCE1 * (&k1v.x)[cmp];
            e = fmaf(FCE3, (&k3v.x)[cmp], e);
            e = fmaf(FCE4, (&k4v.x)[cmp], e);
            e = fmaf(FCE5, (&k5v.x)[cmp], e);
            e = fmaf(FCE6, (&k6v.x)[cmp], e);
            e = fmaf(FCE7, (&kv.x)[cmp],  e);
            e *= dtv;
            const float tol = ATOLF + RTOLF*fmaxf(fabsf((&y0v.x)[cmp]), fabsf((&y1v.x)[cmp]));
            const float r = e / tol;
            errA += (double)r * (double)r;
          }
        }
      }
    }
    __syncthreads();
  }
  if (MODE == 2) red_write(errA, s_red, g_pA);
  gbar(nb);
}

template<int NK>
__device__ void combine(float* __restrict__ dst, const float* __restrict__ base,
                        float dt, const float* const* ks, const float* cf, int nb)
{
  const int gid = blockIdx.x*THREADS + threadIdx.x, nthr = nb*THREADS;
  const float4* b4 = (const float4*)base;
  float4* d4 = (float4*)dst;
  for (int i = gid; i < NTOT/4; i += nthr){
    float4 y = b4[i];
    float sx=0.f, sy=0.f, sz=0.f, sw=0.f;
    #pragma unroll
    for (int j = 0; j < NK; j++){
      float4 k = ((const float4*)ks[j])[i];
      const float c = cf[j];
      sx = fmaf(c,k.x,sx); sy = fmaf(c,k.y,sy); sz = fmaf(c,k.z,sz); sw = fmaf(c,k.w,sw);
    }
    float4 o;
    o.x = fmaf(dt,sx,y.x); o.y = fmaf(dt,sy,y.y); o.z = fmaf(dt,sz,y.z); o.w = fmaf(dt,sw,y.w);
    d4[i] = o;
  }
  gbar(nb);
}

__global__ void __launch_bounds__(THREADS, 2)
odenet_kernel(const float* __restrict__ x, const float* __restrict__ Wconv,
              const float* __restrict__ Wout, const float* __restrict__ bout,
              float* __restrict__ out, int nb)
{
  extern __shared__ char dsm[];
  float* s_w   = (float*)dsm;
  float* s_inp = (float*)(dsm + SW_BYTES);
  double* s_red = (double*)(dsm + SW_BYTES + SIN_BYTES);
  double* s_bc  = s_red + 8;

  const int gid = blockIdx.x*THREADS + threadIdx.x, nthr = nb*THREADS;
  const int tid = threadIdx.x;

  for (int i = tid; i < CC*CC*9; i += THREADS){
    const int ci = i / 288, rem = i - ci*288;
    const int k = rem >> 5, co = rem & 31;
    s_w[i] = Wconv[(co*CC + ci)*9 + k];
  }
  {
    float* Y = SLOT(0);
    for (int i = gid; i < NTOT; i += nthr){
      const int c = (i >> 14) & 31, b = i >> 19;
      float v = 0.f;
      if (c < 3) v = x[(size_t)(b*3 + c)*HWSZ + (i & (HWSZ-1))];
      Y[i] = v;
    }
  }
  gbar(nb);

  // slots: iY0, iScA, iK1, iY1K2 (K2 early / y1 late), K3=4,K4=5,K5=6,K6=7, iK7=8, iScB=9
  int iY0=0, iScA=1, iK1=2, iY1K2=3, iK7=8;
  const int iScB=9;

  conv_tanh<0,0>(SLOT(iY0), SLOT(iK1), 0, 0, 0, 0.f, nb, s_w, s_inp, s_red);   // f0

  {
    const float* Y = SLOT(iY0); const float* F = SLOT(iK1);
    double a=0.0, b=0.0;
    for (int i = gid; i < NTOT; i += nthr){
      const float yi = Y[i], fi = F[i];
      const float sc = ATOLF + RTOLF*fabsf(yi);
      const float r0 = yi/sc, r1 = fi/sc;
      a += (double)r0*r0; b += (double)r1*r1;
    }
    red_write(a, s_red, g_pA); red_write(b, s_red, g_pB);
    gbar(nb);
  }
  const float d0 = sqrtf((float)sum_parts(g_pA, nb, s_bc));
  const float d1 = sqrtf((float)sum_parts(g_pB, nb, s_bc));
  const float h0 = (d0 < 1e-5f || d1 < 1e-5f) ? 1e-6f : 0.01f*d0/d1;
  { const float* ks[1] = { SLOT(iK1) }; const float cf[1] = { 1.f };
    combine<1>(SLOT(iScA), SLOT(iY0), h0, ks, cf, nb); }
  conv_tanh<0,0>(SLOT(iScA), SLOT(iY1K2), 0, 0, 0, 0.f, nb, s_w, s_inp, s_red); // f1
  {
    const float* Y = SLOT(iY0); const float* F0 = SLOT(iK1); const float* F1 = SLOT(iY1K2);
    double a = 0.0;
    for (int i = gid; i < NTOT; i += nthr){
      const float sc = ATOLF + RTOLF*fabsf(Y[i]);
      const float r = (F1[i] - F0[i]) / sc;
      a += (double)r*r;
    }
    red_write(a, s_red, g_pA); gbar(nb);
  }
  const float d2 = sqrtf((float)sum_parts(g_pA, nb, s_bc)) / h0;
  float h1;
  if (d1 <= 1e-15f && d2 <= 1e-15f) h1 = fmaxf(1e-6f, h0*1e-3f);
  else                              h1 = powf(0.01f / fmaxf(d1, d2), 0.2f);
  float dt = fminf(100.f*h0, h1);

  float t = 0.f, last_t = 0.f, dt_used = dt;
  int any = 0, iter = 0;

  while (t < 1.0f && iter < 1000 && dt > 0.f){
    iter++;
    // stage2 input (depends on accept decision, stays standalone)
    { const float* ks[1] = { SLOT(iK1) }; const float cf[1] = { FB21 };
      combine<1>(SLOT(iScA), SLOT(iY0), dt, ks, cf, nb); }
    // k2 conv + fused stage3 input -> ScB
    { const float* eA[2] = { SLOT(iY0), SLOT(iK1) };
      const float cf[2] = { FB31, FB32 };
      conv_tanh<1,2>(SLOT(iScA), SLOT(iY1K2), SLOT(iScB), eA, cf, dt, nb, s_w, s_inp, s_red); }
    // k3 conv + fused stage4 input -> ScA
    { const float* eA[3] = { SLOT(iY0), SLOT(iK1), SLOT(iY1K2) };
      const float cf[3] = { FB41, FB42, FB43 };
      conv_tanh<1,3>(SLOT(iScB), SLOT(4), SLOT(iScA), eA, cf, dt, nb, s_w, s_inp, s_red); }
    // k4 conv + fused stage5 input -> ScB
    { const float* eA[4] = { SLOT(iY0), SLOT(iK1), SLOT(iY1K2), SLOT(4) };
      const float cf[4] = { FB51, FB52, FB53, FB54 };
      conv_tanh<1,4>(SLOT(iScA), SLOT(5), SLOT(iScB), eA, cf, dt, nb, s_w, s_inp, s_red); }
    // k5 conv + fused stage6 input -> ScA
    { const float* eA[5] = { SLOT(iY0), SLOT(iK1), SLOT(iY1K2), SLOT(4), SLOT(5) };
      const float cf[5] = { FB61, FB62, FB63, FB64, FB65 };
      conv_tanh<1,5>(SLOT(iScB), SLOT(6), SLOT(iScA), eA, cf, dt, nb, s_w, s_inp, s_red); }
    // k6 conv + fused y1 -> iY1K2 (overwrites K2; K2 no longer needed)
    { const float* eA[5] = { SLOT(iY0), SLOT(iK1), SLOT(4), SLOT(5), SLOT(6) };
      const float cf[5] = { FCS1, FCS3, FCS4, FCS5, FCS6 };
      conv_tanh<1,5>(SLOT(iScA), SLOT(7), SLOT(iY1K2), eA, cf, dt, nb, s_w, s_inp, s_red); }
    // k7 conv + fused error sum
    { const float* eA[7] = { SLOT(iY0), SLOT(iY1K2), SLOT(iK1), SLOT(4), SLOT(5), SLOT(6), SLOT(7) };
      conv_tanh<2,0>(SLOT(iY1K2), SLOT(iK7), 0, eA, 0, dt, nb, s_w, s_inp, s_red); }

    const double sum = sum_parts(g_pA, nb, s_bc);
    const float ratio = sqrtf((float)(sum / (double)NTOT));
    const float dfac = (ratio < 1.f) ? 1.0f : 0.2f;
    const float factor = fminf(10.f, fmaxf(0.9f * powf(ratio, -0.2f), dfac));
    const float new_dt = dt * factor;
    if (ratio <= 1.f){
      any = 1; dt_used = dt; last_t = t; t = t + dt;
      if (t >= 1.0f){ dt = new_dt; break; }
      int tmp = iY0; iY0 = iY1K2; iY1K2 = tmp;
      tmp = iK1; iK1 = iK7; iK7 = tmp;
    }
    dt = new_dt;
  }

  // interpolate to t=1, fused with global spatial max
  {
    const float xr = any ? (1.0f - last_t) / (t - last_t) : 0.f;
    const float dtu = dt_used;
    const float* Y0 = SLOT(iY0); const float* Y1 = SLOT(iY1K2);
    const float* K1 = SLOT(iK1); const float* K3 = SLOT(4);
    const float* K4 = SLOT(5);   const float* K5 = SLOT(6);
    const float* K6 = SLOT(7);   const float* K7 = SLOT(iK7);
    const int gw = gid >> 5, lane = threadIdx.x & 31, nw = nthr >> 5;
    for (int p = gw; p < BB*CC; p += nw){
      const size_t base = (size_t)p * HWSZ;
      float m = -3.402823466e38f;
      for (int i = lane; i < HWSZ; i += 32){
        const size_t idx = base + i;
        const float y0 = Y0[idx];
        float v = y0;
        if (any){
          const float y1 = Y1[idx];
          const float k1 = K1[idx], k7 = K7[idx];
          float s = FCM1*k1;
          s = fmaf(FCM3, K3[idx], s); s = fmaf(FCM4, K4[idx], s);
          s = fmaf(FCM5, K5[idx], s); s = fmaf(FCM6, K6[idx], s);
          s = fmaf(FCM7, k7, s);
          const float ym = fmaf(dtu, s, y0);
          const float dy0 = k1*dtu, dy1 = k7*dtu;
          const float ca = 2.f*(dy1 - dy0) - 8.f*(y1 + y0) + 16.f*ym;
          const float cb = 5.f*dy0 - 3.f*dy1 + 18.f*y0 + 14.f*y1 - 32.f*ym;
          const float cc = -4.f*dy0 + dy1 - 11.f*y0 - 5.f*y1 + 16.f*ym;
          v = fmaf(fmaf(fmaf(fmaf(ca, xr, cb), xr, cc), xr, dy0), xr, y0);
        }
        m = fmaxf(m, v);
      }
      #pragma unroll
      for (int o = 16; o; o >>= 1) m = fmaxf(m, __shfl_down_sync(0xffffffffu, m, o));
      if (lane == 0) g_feats[p] = m;
    }
    gbar(nb);
  }

  for (int idx = gid; idx < BB*1000; idx += nthr){
    const int b = idx / 1000, n = idx - b*1000;
    const float* f = g_feats + b*CC;
    const float* w = Wout + n*CC;
    float s = bout[n];
    #pragma unroll
    for (int c = 0; c < CC; c++) s = fmaf(f[c], __ldg(w + c), s);
    out[idx] = s;
  }
}

extern "C" void kernel_launch(void* const* d_in, const int* in_sizes, int n_in,
                              void* d_out, int out_size)
{
  const float* x     = (const float*)d_in[0];
  const float* Wconv = (const float*)d_in[1];
  const float* Wout  = (const float*)d_in[2];
  const float* bout  = (const float*)d_in[3];
  float* out = (float*)d_out;

  cudaFuncSetAttribute(odenet_kernel, cudaFuncAttributeMaxDynamicSharedMemorySize, DSM_BYTES);

  int dev = 0; cudaGetDevice(&dev);
  int smCount = 0;
  cudaDeviceGetAttribute(&smCount, cudaDevAttrMultiProcessorCount, dev);
  int bpm = 0;
  cudaOccupancyMaxActiveBlocksPerMultiprocessor(&bpm, odenet_kernel, THREADS, DSM_BYTES);
  if (bpm < 1) bpm = 1;
  int nb = smCount * bpm;
  if (nb > NB_MAX) nb = NB_MAX;
  if (nb < 1) nb = 1;

  odenet_kernel<<<nb, THREADS, DSM_BYTES>>>(x, Wconv, Wout, bout, out, nb);
}